// round 3
// baseline (speedup 1.0000x reference)
#include <cuda_runtime.h>
#include <cstdint>

#define NREPO 30000
#define NUSER 70000
#define NNODE 100000
#define RREL  8
#define HDIM  128
#define B1 (NUSER * RREL)
#define B2 (NREPO * RREL)
#define NB1 ((B1 + 1023) / 1024)
#define NB2 ((B2 + 1023) / 1024)
#define EMAX 1000000

// ---------------- scratch ----------------------------------------------------
__device__ float g_h0[(size_t)NREPO * HDIM];
__device__ float g_h1[(size_t)NNODE * HDIM];
__device__ float g_y1[(size_t)B2 * HDIM];
__device__ float g_sum2[(size_t)B2 * HDIM];
__device__ float g_out2[(size_t)NREPO * HDIM];
__device__ float g_uroot[HDIM];
__device__ int   g_cnt1[B1], g_off1[B1], g_cur1[B1], g_bsum1[NB1];
__device__ int   g_cnt2[B2], g_off2[B2], g_cur2[B2], g_bsum2[NB2];
__device__ int   g_perm1[EMAX];
__device__ int   g_perm2[EMAX];

// ---------------- counting / CSR build ---------------------------------------
__global__ void zero_cnt_k() {
    int i = blockIdx.x * blockDim.x + threadIdx.x;
    if (i < B1) g_cnt1[i] = 0;
    if (i < B2) g_cnt2[i] = 0;
}

__global__ void count_k(const int* __restrict__ er, const int* __restrict__ ea,
                        const int* __restrict__ et, int E) {
    int e = blockIdx.x * blockDim.x + threadIdx.x;
    if (e >= E) return;
    atomicAdd(&g_cnt1[ea[e] * RREL + et[e]], 1);
    atomicAdd(&g_cnt2[er[e] * RREL + et[e]], 1);
}

__global__ void scan_blk_k(const int* __restrict__ cnt, int n, int* __restrict__ off,
                           int* __restrict__ bsum) {
    __shared__ int s[1024];
    int t = threadIdx.x;
    int i = blockIdx.x * 1024 + t;
    int v = (i < n) ? cnt[i] : 0;
    s[t] = v;
    __syncthreads();
#pragma unroll
    for (int d = 1; d < 1024; d <<= 1) {
        int u = (t >= d) ? s[t - d] : 0;
        __syncthreads();
        s[t] += u;
        __syncthreads();
    }
    if (i < n) off[i] = s[t] - v;
    if (t == 1023) bsum[blockIdx.x] = s[1023];
}

__global__ void scan_top_k(int* __restrict__ bsum, int n) {
    __shared__ int s[1024];
    int t = threadIdx.x;
    int v = (t < n) ? bsum[t] : 0;
    s[t] = v;
    __syncthreads();
#pragma unroll
    for (int d = 1; d < 1024; d <<= 1) {
        int u = (t >= d) ? s[t - d] : 0;
        __syncthreads();
        s[t] += u;
        __syncthreads();
    }
    if (t < n) bsum[t] = s[t] - v;
}

__global__ void scan_add_k(int* __restrict__ off, const int* __restrict__ bsum,
                           int* __restrict__ cur, int n) {
    int i = blockIdx.x * blockDim.x + threadIdx.x;
    if (i >= n) return;
    int o = off[i] + bsum[i >> 10];
    off[i] = o;
    cur[i] = o;
}

__global__ void place_k(const int* __restrict__ er, const int* __restrict__ ea,
                        const int* __restrict__ et, int E) {
    int e = blockIdx.x * blockDim.x + threadIdx.x;
    if (e >= E) return;
    int repo = er[e], actor = ea[e], t = et[e];
    int p1 = atomicAdd(&g_cur1[actor * RREL + t], 1);
    g_perm1[p1] = repo;
    int p2 = atomicAdd(&g_cur2[repo * RREL + t], 1);
    g_perm2[p2] = actor;
}

// ---------------- dense small pieces -----------------------------------------
__global__ void mlp_k(const float* __restrict__ x, const float* __restrict__ w,
                      const float* __restrict__ b) {
    int g = blockIdx.x * blockDim.x + threadIdx.x;
    if (g >= NREPO * HDIM) return;
    int n = g >> 7, o = g & 127;
    float acc = b[o];
#pragma unroll
    for (int k = 0; k < 8; k++) acc = fmaf(__ldg(&x[n * 8 + k]), __ldg(&w[k * HDIM + o]), acc);
    g_h0[g] = fmaxf(acc, 0.f);
}

__global__ void uroot_k(const float* __restrict__ mlp_b, const float* __restrict__ root1) {
    int o = threadIdx.x;
    float acc = 0.f;
#pragma unroll 8
    for (int k = 0; k < HDIM; k++)
        acc = fmaf(fmaxf(mlp_b[k], 0.f), root1[k * HDIM + o], acc);
    g_uroot[o] = acc;
}

// layer-1 aggregation: one warp per actor
__global__ void agg1_k(const float* __restrict__ b1) {
    int w = (blockIdx.x * blockDim.x + threadIdx.x) >> 5;
    int lane = threadIdx.x & 31;
    if (w >= NUSER) return;
    float4 acc = *(const float4*)(g_uroot + lane * 4);
#pragma unroll
    for (int r = 0; r < RREL; r++) {
        int bin = w * RREL + r;
        int deg = g_cnt1[bin];
        if (deg == 0) continue;
        int start = g_off1[bin];
        float4 s = make_float4(0.f, 0.f, 0.f, 0.f);
        int j = 0;
        for (; j + 2 <= deg; j += 2) {
            int r0 = __ldg(g_perm1 + start + j);
            int r1 = __ldg(g_perm1 + start + j + 1);
            const float4 v0 = *(const float4*)(g_y1 + (((size_t)r0 * RREL + r) << 7) + lane * 4);
            const float4 v1 = *(const float4*)(g_y1 + (((size_t)r1 * RREL + r) << 7) + lane * 4);
            s.x += v0.x + v1.x; s.y += v0.y + v1.y; s.z += v0.z + v1.z; s.w += v0.w + v1.w;
        }
        if (j < deg) {
            int r0 = __ldg(g_perm1 + start + j);
            const float4 v0 = *(const float4*)(g_y1 + (((size_t)r0 * RREL + r) << 7) + lane * 4);
            s.x += v0.x; s.y += v0.y; s.z += v0.z; s.w += v0.w;
        }
        float inv = 1.0f / (float)deg;
        acc.x = fmaf(s.x, inv, acc.x); acc.y = fmaf(s.y, inv, acc.y);
        acc.z = fmaf(s.z, inv, acc.z); acc.w = fmaf(s.w, inv, acc.w);
    }
    const float4 bb = *(const float4*)(b1 + lane * 4);
    acc.x = fmaxf(acc.x + bb.x, 0.f); acc.y = fmaxf(acc.y + bb.y, 0.f);
    acc.z = fmaxf(acc.z + bb.z, 0.f); acc.w = fmaxf(acc.w + bb.w, 0.f);
    *(float4*)(g_h1 + (((size_t)(NREPO + w)) << 7) + lane * 4) = acc;
}

// layer-2 aggregation: one warp per repo
__global__ void agg2_k() {
    int w = (blockIdx.x * blockDim.x + threadIdx.x) >> 5;
    int lane = threadIdx.x & 31;
    if (w >= NREPO) return;
#pragma unroll
    for (int r = 0; r < RREL; r++) {
        int bin = w * RREL + r;
        int deg = g_cnt2[bin];
        float4 s = make_float4(0.f, 0.f, 0.f, 0.f);
        int start = g_off2[bin];
        int j = 0;
        for (; j + 2 <= deg; j += 2) {
            int a0 = __ldg(g_perm2 + start + j);
            int a1 = __ldg(g_perm2 + start + j + 1);
            const float4 v0 = *(const float4*)(g_h1 + (((size_t)(NREPO + a0)) << 7) + lane * 4);
            const float4 v1 = *(const float4*)(g_h1 + (((size_t)(NREPO + a1)) << 7) + lane * 4);
            s.x += v0.x + v1.x; s.y += v0.y + v1.y; s.z += v0.z + v1.z; s.w += v0.w + v1.w;
        }
        if (j < deg) {
            int a0 = __ldg(g_perm2 + start + j);
            const float4 v0 = *(const float4*)(g_h1 + (((size_t)(NREPO + a0)) << 7) + lane * 4);
            s.x += v0.x; s.y += v0.y; s.z += v0.z; s.w += v0.w;
        }
        float inv = (deg > 0) ? 1.0f / (float)deg : 0.f;
        s.x *= inv; s.y *= inv; s.z *= inv; s.w *= inv;
        *(float4*)(g_sum2 + ((size_t)bin << 7) + lane * 4) = s;
    }
}

// finalize layer 2 + classifier
__global__ void fincls_k(const float* __restrict__ b2, const float* __restrict__ clsw,
                         const float* __restrict__ clsb, float* __restrict__ out) {
    int j = blockIdx.x;
    int t = threadIdx.x;
    float v = fmaxf(g_out2[(size_t)j * HDIM + t] + b2[t], 0.f);
    float p0 = v * clsw[t * 2 + 0];
    float p1 = v * clsw[t * 2 + 1];
#pragma unroll
    for (int o = 16; o; o >>= 1) {
        p0 += __shfl_xor_sync(0xffffffffu, p0, o);
        p1 += __shfl_xor_sync(0xffffffffu, p1, o);
    }
    __shared__ float s0[4], s1[4];
    if ((t & 31) == 0) { s0[t >> 5] = p0; s1[t >> 5] = p1; }
    __syncthreads();
    if (t == 0) {
        out[j * 2 + 0] = s0[0] + s0[1] + s0[2] + s0[3] + clsb[0];
        out[j * 2 + 1] = s1[0] + s1[1] + s1[2] + s1[3] + clsb[1];
    }
}

// ================= 3xTF32 tensor-core GEMM ===================================
// C[M x 128] = A[M x K=128 (lda)] @ B[128 x 128], z-batched.
// mode: 0 = store, 1 = store relu(acc + bias[col]), 2 = red.global.add.
// Accuracy: A = Ah + Al, B = Bh + Bl (tf32 splits); C = AhBh + AlBh + AhBl.

#define KSTG 16
#define SPAD 20   // row pitch in floats (16 + 4) — conflict-free fragment LDS

__device__ __forceinline__ unsigned f2tf(float x) {
    unsigned r;
    asm("cvt.rna.tf32.f32 %0, %1;" : "=r"(r) : "f"(x));
    return r;
}

__device__ __forceinline__ void split_tf(float x, float& hi, float& lo) {
    unsigned h = f2tf(x);
    hi = __uint_as_float(h);
    lo = __uint_as_float(f2tf(x - hi));
}

__device__ __forceinline__ void mma_tf32(float c[4], const unsigned a[4], const unsigned b[2]) {
    asm volatile(
        "mma.sync.aligned.m16n8k8.row.col.f32.tf32.tf32.f32 "
        "{%0,%1,%2,%3}, {%4,%5,%6,%7}, {%8,%9}, {%0,%1,%2,%3};"
        : "+f"(c[0]), "+f"(c[1]), "+f"(c[2]), "+f"(c[3])
        : "r"(a[0]), "r"(a[1]), "r"(a[2]), "r"(a[3]), "r"(b[0]), "r"(b[1]));
}

__device__ __forceinline__ void red_add_v2(float* p, float a, float b) {
    asm volatile("red.global.add.v2.f32 [%0], {%1,%2};" :: "l"(p), "f"(a), "f"(b) : "memory");
}

__global__ void __launch_bounds__(256)
mma_k(const float* __restrict__ A, int M, int lda, int aOffZ,
      const float* __restrict__ B, long bStrideZ,
      float* __restrict__ C, int cstride, int cOffZ, int mode,
      const float* __restrict__ bias) {
    extern __shared__ float sm[];
    float* AH = sm;                // [2][128][SPAD]
    float* AL = sm + 5120;
    float* BH = sm + 10240;       // [2][128(n)][SPAD(k)]  (transposed)
    float* BL = sm + 15360;

    const int tid = threadIdx.x;
    const int lane = tid & 31;
    const int warp = tid >> 5;
    const int wm = (warp >> 2) * 64;
    const int wn = (warp & 3) * 32;
    const int z = blockIdx.z;
    const float* Ab = A + (size_t)z * aOffZ;
    const float* Bb = B + (size_t)z * bStrideZ;
    const int cOff = z * cOffZ;
    const int m0 = blockIdx.x * 128;

    // per-thread load geometry (2 vectors each for A and B per stage)
    const int ar0 = tid >> 2, akq = (tid & 3) * 4;          // A: q = tid
    const int ar1 = (tid + 256) >> 2;                       //     q = tid+256
    const int bk0 = tid >> 5, bn0 = (tid & 31) * 4;         // B: q = tid
    const int bk1 = (tid + 256) >> 5, bn1 = bn0;            //     q = tid+256

    float acc[4][4][4];
#pragma unroll
    for (int i = 0; i < 4; i++)
#pragma unroll
        for (int j = 0; j < 4; j++)
#pragma unroll
            for (int k = 0; k < 4; k++) acc[i][j][k] = 0.f;

    float4 ra0, ra1, rb0, rb1;

    auto fetch = [&](int k0) {
        ra0 = (m0 + ar0 < M) ? *(const float4*)(Ab + (size_t)(m0 + ar0) * lda + k0 + akq)
                             : make_float4(0.f, 0.f, 0.f, 0.f);
        ra1 = (m0 + ar1 < M) ? *(const float4*)(Ab + (size_t)(m0 + ar1) * lda + k0 + akq)
                             : make_float4(0.f, 0.f, 0.f, 0.f);
        rb0 = *(const float4*)(Bb + (size_t)(k0 + bk0) * 128 + bn0);
        rb1 = *(const float4*)(Bb + (size_t)(k0 + bk1) * 128 + bn1);
    };

    auto store = [&](int buf) {
        int base = buf * 2560;
        float h, l;
        // A vec0
        {
            int o = base + ar0 * SPAD + akq;
            float4 hv, lv;
            split_tf(ra0.x, hv.x, lv.x); split_tf(ra0.y, hv.y, lv.y);
            split_tf(ra0.z, hv.z, lv.z); split_tf(ra0.w, hv.w, lv.w);
            *(float4*)(AH + o) = hv; *(float4*)(AL + o) = lv;
        }
        // A vec1
        {
            int o = base + ar1 * SPAD + akq;
            float4 hv, lv;
            split_tf(ra1.x, hv.x, lv.x); split_tf(ra1.y, hv.y, lv.y);
            split_tf(ra1.z, hv.z, lv.z); split_tf(ra1.w, hv.w, lv.w);
            *(float4*)(AH + o) = hv; *(float4*)(AL + o) = lv;
        }
        // B vec0 (transpose: [n][k])
        split_tf(rb0.x, h, l); BH[base + (bn0 + 0) * SPAD + bk0] = h; BL[base + (bn0 + 0) * SPAD + bk0] = l;
        split_tf(rb0.y, h, l); BH[base + (bn0 + 1) * SPAD + bk0] = h; BL[base + (bn0 + 1) * SPAD + bk0] = l;
        split_tf(rb0.z, h, l); BH[base + (bn0 + 2) * SPAD + bk0] = h; BL[base + (bn0 + 2) * SPAD + bk0] = l;
        split_tf(rb0.w, h, l); BH[base + (bn0 + 3) * SPAD + bk0] = h; BL[base + (bn0 + 3) * SPAD + bk0] = l;
        // B vec1
        split_tf(rb1.x, h, l); BH[base + (bn1 + 0) * SPAD + bk1] = h; BL[base + (bn1 + 0) * SPAD + bk1] = l;
        split_tf(rb1.y, h, l); BH[base + (bn1 + 1) * SPAD + bk1] = h; BL[base + (bn1 + 1) * SPAD + bk1] = l;
        split_tf(rb1.z, h, l); BH[base + (bn1 + 2) * SPAD + bk1] = h; BL[base + (bn1 + 2) * SPAD + bk1] = l;
        split_tf(rb1.w, h, l); BH[base + (bn1 + 3) * SPAD + bk1] = h; BL[base + (bn1 + 3) * SPAD + bk1] = l;
    };

    auto compute = [&](int buf) {
        int base = buf * 2560;
#pragma unroll
        for (int ks = 0; ks < KSTG; ks += 8) {
            unsigned Ah[4][4], Al[4][4], Bh[4][2], Bl[4][2];
            int kb = ks + (lane & 3);
#pragma unroll
            for (int mf = 0; mf < 4; mf++) {
                int r = wm + mf * 16 + (lane >> 2);
                int i0 = base + r * SPAD + kb;
                int i1 = i0 + 8 * SPAD;
                Ah[mf][0] = __float_as_uint(AH[i0]);
                Ah[mf][1] = __float_as_uint(AH[i1]);
                Ah[mf][2] = __float_as_uint(AH[i0 + 4]);
                Ah[mf][3] = __float_as_uint(AH[i1 + 4]);
                Al[mf][0] = __float_as_uint(AL[i0]);
                Al[mf][1] = __float_as_uint(AL[i1]);
                Al[mf][2] = __float_as_uint(AL[i0 + 4]);
                Al[mf][3] = __float_as_uint(AL[i1 + 4]);
            }
#pragma unroll
            for (int nf = 0; nf < 4; nf++) {
                int n = wn + nf * 8 + (lane >> 2);
                int j0 = base + n * SPAD + kb;
                Bh[nf][0] = __float_as_uint(BH[j0]);
                Bh[nf][1] = __float_as_uint(BH[j0 + 4]);
                Bl[nf][0] = __float_as_uint(BL[j0]);
                Bl[nf][1] = __float_as_uint(BL[j0 + 4]);
            }
#pragma unroll
            for (int mf = 0; mf < 4; mf++)
#pragma unroll
                for (int nf = 0; nf < 4; nf++) {
                    mma_tf32(acc[mf][nf], Ah[mf], Bh[nf]);
                    mma_tf32(acc[mf][nf], Al[mf], Bh[nf]);
                    mma_tf32(acc[mf][nf], Ah[mf], Bl[nf]);
                }
        }
    };

    // K = 128 fixed: 8 stages of 16
    fetch(0);
    store(0);
    __syncthreads();
#pragma unroll 1
    for (int kt = 0; kt < 8; kt++) {
        int buf = kt & 1;
        if (kt + 1 < 8) fetch((kt + 1) * KSTG);
        compute(buf);
        if (kt + 1 < 8) {
            store(buf ^ 1);
            __syncthreads();
        }
    }

    // epilogue
#pragma unroll
    for (int mf = 0; mf < 4; mf++) {
#pragma unroll
        for (int nf = 0; nf < 4; nf++) {
            int r0 = m0 + wm + mf * 16 + (lane >> 2);
            int r1 = r0 + 8;
            int cl = wn + nf * 8 + (lane & 3) * 2;     // col within 128
            float v0 = acc[mf][nf][0], v1 = acc[mf][nf][1];
            float v2 = acc[mf][nf][2], v3 = acc[mf][nf][3];
            if (mode == 1) {
                float b0 = bias[cl], b1v = bias[cl + 1];
                v0 = fmaxf(v0 + b0, 0.f); v1 = fmaxf(v1 + b1v, 0.f);
                v2 = fmaxf(v2 + b0, 0.f); v3 = fmaxf(v3 + b1v, 0.f);
            }
            if (r0 < M) {
                float* p = C + (size_t)r0 * cstride + cOff + cl;
                if (mode == 2) red_add_v2(p, v0, v1);
                else { p[0] = v0; p[1] = v1; }
            }
            if (r1 < M) {
                float* p = C + (size_t)r1 * cstride + cOff + cl;
                if (mode == 2) red_add_v2(p, v2, v3);
                else { p[0] = v2; p[1] = v3; }
            }
        }
    }
}

#define MMA_SMEM (20480 * 4)

// ---------------- driver -----------------------------------------------------
extern "C" void kernel_launch(void* const* d_in, const int* in_sizes, int n_in,
                              void* d_out, int out_size) {
    const float* x     = (const float*)d_in[0];
    const int*   er    = (const int*)d_in[1];
    const int*   ea    = (const int*)d_in[2];
    const int*   et    = (const int*)d_in[3];
    const float* mlp_w = (const float*)d_in[4];
    const float* mlp_b = (const float*)d_in[5];
    const float* w1    = (const float*)d_in[6];
    const float* root1 = (const float*)d_in[7];
    const float* b1    = (const float*)d_in[8];
    const float* w2    = (const float*)d_in[9];
    const float* root2 = (const float*)d_in[10];
    const float* b2    = (const float*)d_in[11];
    const float* cls_w = (const float*)d_in[12];
    const float* cls_b = (const float*)d_in[13];
    int E = in_sizes[1];
    float* out = (float*)d_out;

    void *pH0, *pH1, *pS2, *pO2, *pY1, *pOff1, *pOff2, *pBs1, *pBs2, *pCnt1, *pCnt2, *pCur1, *pCur2;
    cudaGetSymbolAddress(&pH0, g_h0);
    cudaGetSymbolAddress(&pH1, g_h1);
    cudaGetSymbolAddress(&pY1, g_y1);
    cudaGetSymbolAddress(&pS2, g_sum2);
    cudaGetSymbolAddress(&pO2, g_out2);
    cudaGetSymbolAddress(&pCnt1, g_cnt1);
    cudaGetSymbolAddress(&pCnt2, g_cnt2);
    cudaGetSymbolAddress(&pOff1, g_off1);
    cudaGetSymbolAddress(&pOff2, g_off2);
    cudaGetSymbolAddress(&pCur1, g_cur1);
    cudaGetSymbolAddress(&pCur2, g_cur2);
    cudaGetSymbolAddress(&pBs1, g_bsum1);
    cudaGetSymbolAddress(&pBs2, g_bsum2);

    cudaFuncSetAttribute(mma_k, cudaFuncAttributeMaxDynamicSharedMemorySize, MMA_SMEM);

    // --- CSR construction ---
    zero_cnt_k<<<(B1 + 255) / 256, 256>>>();
    count_k<<<(E + 255) / 256, 256>>>(er, ea, et, E);
    scan_blk_k<<<NB1, 1024>>>((const int*)pCnt1, B1, (int*)pOff1, (int*)pBs1);
    scan_blk_k<<<NB2, 1024>>>((const int*)pCnt2, B2, (int*)pOff2, (int*)pBs2);
    scan_top_k<<<1, 1024>>>((int*)pBs1, NB1);
    scan_top_k<<<1, 1024>>>((int*)pBs2, NB2);
    scan_add_k<<<(B1 + 255) / 256, 256>>>((int*)pOff1, (const int*)pBs1, (int*)pCur1, B1);
    scan_add_k<<<(B2 + 255) / 256, 256>>>((int*)pOff2, (const int*)pBs2, (int*)pCur2, B2);
    place_k<<<(E + 255) / 256, 256>>>(er, ea, et, E);

    // --- dense front ---
    mlp_k<<<(NREPO * HDIM + 255) / 256, 256>>>(x, mlp_w, mlp_b);
    uroot_k<<<1, HDIM>>>(mlp_b, root1);

    const int GB = (NREPO + 127) / 128;   // 235
    // y1[repo,r] = h0 @ W1[r]
    mma_k<<<dim3(GB, 1, RREL), 256, MMA_SMEM>>>(
        (const float*)pH0, NREPO, HDIM, 0, w1, (long)HDIM * HDIM,
        (float*)pY1, RREL * HDIM, HDIM, 0, nullptr);
    // h1[repo] = relu(h0 @ root1 + b1)   (fused epilogue)
    mma_k<<<dim3(GB, 1, 1), 256, MMA_SMEM>>>(
        (const float*)pH0, NREPO, HDIM, 0, root1, 0,
        (float*)pH1, HDIM, 0, 1, b1);

    // layer-1 aggregation (actor rows of h1)
    agg1_k<<<(NUSER + 7) / 8, 256>>>(b1);

    // layer-2 aggregation
    agg2_k<<<(NREPO + 7) / 8, 256>>>();

    // out2 = h1[:NREPO] @ root2
    mma_k<<<dim3(GB, 1, 1), 256, MMA_SMEM>>>(
        (const float*)pH1, NREPO, HDIM, 0, root2, 0,
        (float*)pO2, HDIM, 0, 0, nullptr);
    // out2 += mean2 @ w2   (K split over z, red.add epilogue)
    mma_k<<<dim3(GB, 1, RREL), 256, MMA_SMEM>>>(
        (const float*)pS2, NREPO, RREL * HDIM, HDIM, w2, (long)HDIM * HDIM,
        (float*)pO2, HDIM, 0, 2, nullptr);

    // relu + bias + classifier
    fincls_k<<<NREPO, HDIM>>>(b2, cls_w, cls_b, out);
}

// round 5
// speedup vs baseline: 1.6480x; 1.6480x over previous
#include <cuda_runtime.h>
#include <cuda_bf16.h>
#include <cstdint>

#define NREPO 30000
#define NUSER 70000
#define NNODE 100000
#define RREL  8
#define HDIM  128
#define B1 (NUSER * RREL)
#define B2 (NREPO * RREL)
#define NB1 ((B1 + 1023) / 1024)
#define NB2 ((B2 + 1023) / 1024)
#define EMAX 1000000

// ---------------- scratch ----------------------------------------------------
__device__ float g_h0[(size_t)NREPO * HDIM];
__device__ float g_h1[(size_t)NNODE * HDIM];
__device__ float g_y1[(size_t)B2 * HDIM];
__device__ float g_sum2[(size_t)B2 * HDIM];
__device__ float g_out2[(size_t)NREPO * HDIM];
__device__ float g_uroot[HDIM];
__device__ int   g_cnt1[B1], g_off1[B1], g_cur1[B1], g_bsum1[NB1];
__device__ int   g_cnt2[B2], g_off2[B2], g_cur2[B2], g_bsum2[NB2];
__device__ int   g_perm1[EMAX];
__device__ int   g_perm2[EMAX];

// ---------------- counting / CSR build ---------------------------------------
__global__ void zero_cnt_k() {
    int i = blockIdx.x * blockDim.x + threadIdx.x;
    if (i < B1) g_cnt1[i] = 0;
    if (i < B2) g_cnt2[i] = 0;
}

__global__ void count_k(const int* __restrict__ er, const int* __restrict__ ea,
                        const int* __restrict__ et, int E) {
    int e = blockIdx.x * blockDim.x + threadIdx.x;
    if (e >= E) return;
    atomicAdd(&g_cnt1[ea[e] * RREL + et[e]], 1);
    atomicAdd(&g_cnt2[er[e] * RREL + et[e]], 1);
}

__global__ void scan_blk_k(const int* __restrict__ cnt, int n, int* __restrict__ off,
                           int* __restrict__ bsum) {
    __shared__ int s[1024];
    int t = threadIdx.x;
    int i = blockIdx.x * 1024 + t;
    int v = (i < n) ? cnt[i] : 0;
    s[t] = v;
    __syncthreads();
#pragma unroll
    for (int d = 1; d < 1024; d <<= 1) {
        int u = (t >= d) ? s[t - d] : 0;
        __syncthreads();
        s[t] += u;
        __syncthreads();
    }
    if (i < n) off[i] = s[t] - v;
    if (t == 1023) bsum[blockIdx.x] = s[1023];
}

__global__ void scan_top_k(int* __restrict__ bsum, int n) {
    __shared__ int s[1024];
    int t = threadIdx.x;
    int v = (t < n) ? bsum[t] : 0;
    s[t] = v;
    __syncthreads();
#pragma unroll
    for (int d = 1; d < 1024; d <<= 1) {
        int u = (t >= d) ? s[t - d] : 0;
        __syncthreads();
        s[t] += u;
        __syncthreads();
    }
    if (t < n) bsum[t] = s[t] - v;
}

__global__ void scan_add_k(int* __restrict__ off, const int* __restrict__ bsum,
                           int* __restrict__ cur, int n) {
    int i = blockIdx.x * blockDim.x + threadIdx.x;
    if (i >= n) return;
    int o = off[i] + bsum[i >> 10];
    off[i] = o;
    cur[i] = o;
}

__global__ void place_k(const int* __restrict__ er, const int* __restrict__ ea,
                        const int* __restrict__ et, int E) {
    int e = blockIdx.x * blockDim.x + threadIdx.x;
    if (e >= E) return;
    int repo = er[e], actor = ea[e], t = et[e];
    int p1 = atomicAdd(&g_cur1[actor * RREL + t], 1);
    g_perm1[p1] = repo;
    int p2 = atomicAdd(&g_cur2[repo * RREL + t], 1);
    g_perm2[p2] = actor;
}

// ---------------- dense small pieces -----------------------------------------
__global__ void mlp_k(const float* __restrict__ x, const float* __restrict__ w,
                      const float* __restrict__ b) {
    int g = blockIdx.x * blockDim.x + threadIdx.x;
    if (g >= NREPO * HDIM) return;
    int n = g >> 7, o = g & 127;
    float acc = b[o];
#pragma unroll
    for (int k = 0; k < 8; k++) acc = fmaf(__ldg(&x[n * 8 + k]), __ldg(&w[k * HDIM + o]), acc);
    g_h0[g] = fmaxf(acc, 0.f);
}

__global__ void uroot_k(const float* __restrict__ mlp_b, const float* __restrict__ root1) {
    int o = threadIdx.x;
    float acc = 0.f;
#pragma unroll 8
    for (int k = 0; k < HDIM; k++)
        acc = fmaf(fmaxf(mlp_b[k], 0.f), root1[k * HDIM + o], acc);
    g_uroot[o] = acc;
}

// layer-1 aggregation: one warp per actor
__global__ void agg1_k(const float* __restrict__ b1) {
    int w = (blockIdx.x * blockDim.x + threadIdx.x) >> 5;
    int lane = threadIdx.x & 31;
    if (w >= NUSER) return;
    float4 acc = *(const float4*)(g_uroot + lane * 4);
#pragma unroll
    for (int r = 0; r < RREL; r++) {
        int bin = w * RREL + r;
        int deg = g_cnt1[bin];
        if (deg == 0) continue;
        int start = g_off1[bin];
        float4 s = make_float4(0.f, 0.f, 0.f, 0.f);
        int j = 0;
        for (; j + 2 <= deg; j += 2) {
            int r0 = __ldg(g_perm1 + start + j);
            int r1 = __ldg(g_perm1 + start + j + 1);
            const float4 v0 = *(const float4*)(g_y1 + (((size_t)r0 * RREL + r) << 7) + lane * 4);
            const float4 v1 = *(const float4*)(g_y1 + (((size_t)r1 * RREL + r) << 7) + lane * 4);
            s.x += v0.x + v1.x; s.y += v0.y + v1.y; s.z += v0.z + v1.z; s.w += v0.w + v1.w;
        }
        if (j < deg) {
            int r0 = __ldg(g_perm1 + start + j);
            const float4 v0 = *(const float4*)(g_y1 + (((size_t)r0 * RREL + r) << 7) + lane * 4);
            s.x += v0.x; s.y += v0.y; s.z += v0.z; s.w += v0.w;
        }
        float inv = 1.0f / (float)deg;
        acc.x = fmaf(s.x, inv, acc.x); acc.y = fmaf(s.y, inv, acc.y);
        acc.z = fmaf(s.z, inv, acc.z); acc.w = fmaf(s.w, inv, acc.w);
    }
    const float4 bb = *(const float4*)(b1 + lane * 4);
    acc.x = fmaxf(acc.x + bb.x, 0.f); acc.y = fmaxf(acc.y + bb.y, 0.f);
    acc.z = fmaxf(acc.z + bb.z, 0.f); acc.w = fmaxf(acc.w + bb.w, 0.f);
    *(float4*)(g_h1 + (((size_t)(NREPO + w)) << 7) + lane * 4) = acc;
}

// layer-2 aggregation: one warp per repo
__global__ void agg2_k() {
    int w = (blockIdx.x * blockDim.x + threadIdx.x) >> 5;
    int lane = threadIdx.x & 31;
    if (w >= NREPO) return;
#pragma unroll
    for (int r = 0; r < RREL; r++) {
        int bin = w * RREL + r;
        int deg = g_cnt2[bin];
        float4 s = make_float4(0.f, 0.f, 0.f, 0.f);
        int start = g_off2[bin];
        int j = 0;
        for (; j + 2 <= deg; j += 2) {
            int a0 = __ldg(g_perm2 + start + j);
            int a1 = __ldg(g_perm2 + start + j + 1);
            const float4 v0 = *(const float4*)(g_h1 + (((size_t)(NREPO + a0)) << 7) + lane * 4);
            const float4 v1 = *(const float4*)(g_h1 + (((size_t)(NREPO + a1)) << 7) + lane * 4);
            s.x += v0.x + v1.x; s.y += v0.y + v1.y; s.z += v0.z + v1.z; s.w += v0.w + v1.w;
        }
        if (j < deg) {
            int a0 = __ldg(g_perm2 + start + j);
            const float4 v0 = *(const float4*)(g_h1 + (((size_t)(NREPO + a0)) << 7) + lane * 4);
            s.x += v0.x; s.y += v0.y; s.z += v0.z; s.w += v0.w;
        }
        float inv = (deg > 0) ? 1.0f / (float)deg : 0.f;
        s.x *= inv; s.y *= inv; s.z *= inv; s.w *= inv;
        *(float4*)(g_sum2 + ((size_t)bin << 7) + lane * 4) = s;
    }
}

// finalize layer 2 + classifier
__global__ void fincls_k(const float* __restrict__ b2, const float* __restrict__ clsw,
                         const float* __restrict__ clsb, float* __restrict__ out) {
    int j = blockIdx.x;
    int t = threadIdx.x;
    float v = fmaxf(g_out2[(size_t)j * HDIM + t] + b2[t], 0.f);
    float p0 = v * clsw[t * 2 + 0];
    float p1 = v * clsw[t * 2 + 1];
#pragma unroll
    for (int o = 16; o; o >>= 1) {
        p0 += __shfl_xor_sync(0xffffffffu, p0, o);
        p1 += __shfl_xor_sync(0xffffffffu, p1, o);
    }
    __shared__ float s0[4], s1[4];
    if ((t & 31) == 0) { s0[t >> 5] = p0; s1[t >> 5] = p1; }
    __syncthreads();
    if (t == 0) {
        out[j * 2 + 0] = s0[0] + s0[1] + s0[2] + s0[3] + clsb[0];
        out[j * 2 + 1] = s1[0] + s1[1] + s1[2] + s1[3] + clsb[1];
    }
}

// ================= bf16 3-term tensor-core GEMM ==============================
// C[M x 128] = A[M x 128 (lda)] @ B[128 x 128], z-batched.
// A = Ah + Al, B = Bh + Bl (bf16 splits); C = AhBh + AlBh + AhBl (fp32 acc).
// mode: 0 = store, 1 = store relu(acc + bias[col]), 2 = red.global.add.

#define PITCH 136              // bf16 elems per smem row (128 + 8 pad)
#define AH_OFF 0               // byte offsets of the 4 planes (128 x PITCH bf16)
#define AL_OFF 34816
#define BH_OFF 69632
#define BL_OFF 104448
#define MMA_SMEM 139264

__device__ __forceinline__ uint32_t smem_u32(const void* p) {
    uint32_t a;
    asm("{ .reg .u64 t; cvta.to.shared.u64 t, %1; cvt.u32.u64 %0, t; }" : "=r"(a) : "l"(p));
    return a;
}

__device__ __forceinline__ void ldsm_x4(unsigned r[4], uint32_t addr) {
    asm volatile("ldmatrix.sync.aligned.m8n8.x4.shared.b16 {%0,%1,%2,%3}, [%4];"
                 : "=r"(r[0]), "=r"(r[1]), "=r"(r[2]), "=r"(r[3]) : "r"(addr));
}

__device__ __forceinline__ void ldsm_x4_t(unsigned r[4], uint32_t addr) {
    asm volatile("ldmatrix.sync.aligned.m8n8.x4.trans.shared.b16 {%0,%1,%2,%3}, [%4];"
                 : "=r"(r[0]), "=r"(r[1]), "=r"(r[2]), "=r"(r[3]) : "r"(addr));
}

__device__ __forceinline__ void mma_bf16(float c[4], const unsigned a[4], const unsigned* b) {
    asm volatile(
        "mma.sync.aligned.m16n8k16.row.col.f32.bf16.bf16.f32 "
        "{%0,%1,%2,%3}, {%4,%5,%6,%7}, {%8,%9}, {%0,%1,%2,%3};"
        : "+f"(c[0]), "+f"(c[1]), "+f"(c[2]), "+f"(c[3])
        : "r"(a[0]), "r"(a[1]), "r"(a[2]), "r"(a[3]), "r"(b[0]), "r"(b[1]));
}

__device__ __forceinline__ void red_add_v2(float* p, float a, float b) {
    asm volatile("red.global.add.v2.f32 [%0], {%1,%2};" :: "l"(p), "f"(a), "f"(b) : "memory");
}

// split float -> (hi bf16, lo bf16) as ushorts
__device__ __forceinline__ void sp_bf(float x, unsigned short& h, unsigned short& l) {
    __nv_bfloat16 hb = __float2bfloat16_rn(x);
    h = __bfloat16_as_ushort(hb);
    l = __bfloat16_as_ushort(__float2bfloat16_rn(x - __bfloat162float(hb)));
}

__global__ void __launch_bounds__(256)
bmma_k(const float* __restrict__ A, int M, int lda, int aOffZ,
       const float* __restrict__ B, long bStrideZ,
       float* __restrict__ C, int cstride, int cOffZ, int mode,
       const float* __restrict__ bias) {
    extern __shared__ char sm[];
    const uint32_t sb = smem_u32(sm);

    const int tid = threadIdx.x;
    const int lane = tid & 31;
    const int warp = tid >> 5;
    const int wm = (warp >> 2) * 64;
    const int wn = (warp & 3) * 32;
    const int z = blockIdx.z;
    const float* Ab = A + (size_t)z * aOffZ;
    const float* Bb = B + (size_t)z * bStrideZ;
    const int cOff = z * cOffZ;
    const int m0 = blockIdx.x * 128;

    // ---- load + split + store (one shot, whole K=128) ----
#pragma unroll
    for (int it = 0; it < 16; it++) {
        int v = tid + it * 256;          // 0..4095
        int row = v >> 5;                // 0..127
        int c4 = (v & 31) * 4;           // 0..124
        // A tile row (guarded)
        float4 fa = (m0 + row < M) ? *(const float4*)(Ab + (size_t)(m0 + row) * lda + c4)
                                   : make_float4(0.f, 0.f, 0.f, 0.f);
        unsigned short h0, h1, h2, h3, l0, l1, l2, l3;
        sp_bf(fa.x, h0, l0); sp_bf(fa.y, h1, l1); sp_bf(fa.z, h2, l2); sp_bf(fa.w, h3, l3);
        int off = (row * PITCH + c4) * 2;
        *(uint2*)(sm + AH_OFF + off) = make_uint2((unsigned)h0 | ((unsigned)h1 << 16),
                                                  (unsigned)h2 | ((unsigned)h3 << 16));
        *(uint2*)(sm + AL_OFF + off) = make_uint2((unsigned)l0 | ((unsigned)l1 << 16),
                                                  (unsigned)l2 | ((unsigned)l3 << 16));
        // B row (k = row)
        float4 fb = *(const float4*)(Bb + (size_t)row * 128 + c4);
        sp_bf(fb.x, h0, l0); sp_bf(fb.y, h1, l1); sp_bf(fb.z, h2, l2); sp_bf(fb.w, h3, l3);
        *(uint2*)(sm + BH_OFF + off) = make_uint2((unsigned)h0 | ((unsigned)h1 << 16),
                                                  (unsigned)h2 | ((unsigned)h3 << 16));
        *(uint2*)(sm + BL_OFF + off) = make_uint2((unsigned)l0 | ((unsigned)l1 << 16),
                                                  (unsigned)l2 | ((unsigned)l3 << 16));
    }
    __syncthreads();

    float acc[4][4][4];
#pragma unroll
    for (int i = 0; i < 4; i++)
#pragma unroll
        for (int j = 0; j < 4; j++)
#pragma unroll
            for (int k = 0; k < 4; k++) acc[i][j][k] = 0.f;

    // per-lane ldmatrix geometry
    const int lrow = lane & 15;          // row (A) / k (B) within 16
    const int lhalf = (lane >> 4) * 8;   // +8 elems for upper address group

    // ---- main loop: 8 chunks of k16 ----
#pragma unroll 1
    for (int kc = 0; kc < 8; kc++) {
        int k0 = kc * 16;
        unsigned Ah[4][4], Al[4][4], Bh[2][4], Bl[2][4];
#pragma unroll
        for (int mf = 0; mf < 4; mf++) {
            uint32_t a = sb + ((wm + mf * 16 + lrow) * PITCH + k0 + lhalf) * 2;
            ldsm_x4(Ah[mf], a + AH_OFF);
            ldsm_x4(Al[mf], a + AL_OFF);
        }
#pragma unroll
        for (int np = 0; np < 2; np++) {
            uint32_t a = sb + ((k0 + lrow) * PITCH + wn + np * 16 + lhalf) * 2;
            ldsm_x4_t(Bh[np], a + BH_OFF);
            ldsm_x4_t(Bl[np], a + BL_OFF);
        }
#pragma unroll
        for (int mf = 0; mf < 4; mf++)
#pragma unroll
            for (int nf = 0; nf < 4; nf++) {
                const unsigned* bh = &Bh[nf >> 1][(nf & 1) * 2];
                const unsigned* bl = &Bl[nf >> 1][(nf & 1) * 2];
                mma_bf16(acc[mf][nf], Ah[mf], bh);
                mma_bf16(acc[mf][nf], Al[mf], bh);
                mma_bf16(acc[mf][nf], Ah[mf], bl);
            }
    }

    // ---- epilogue ----
#pragma unroll
    for (int mf = 0; mf < 4; mf++) {
#pragma unroll
        for (int nf = 0; nf < 4; nf++) {
            int r0 = m0 + wm + mf * 16 + (lane >> 2);
            int r1 = r0 + 8;
            int cl = wn + nf * 8 + (lane & 3) * 2;
            float v0 = acc[mf][nf][0], v1 = acc[mf][nf][1];
            float v2 = acc[mf][nf][2], v3 = acc[mf][nf][3];
            if (mode == 1) {
                float b0 = bias[cl], b1v = bias[cl + 1];
                v0 = fmaxf(v0 + b0, 0.f); v1 = fmaxf(v1 + b1v, 0.f);
                v2 = fmaxf(v2 + b0, 0.f); v3 = fmaxf(v3 + b1v, 0.f);
            }
            if (r0 < M) {
                float* p = C + (size_t)r0 * cstride + cOff + cl;
                if (mode == 2) red_add_v2(p, v0, v1);
                else { p[0] = v0; p[1] = v1; }
            }
            if (r1 < M) {
                float* p = C + (size_t)r1 * cstride + cOff + cl;
                if (mode == 2) red_add_v2(p, v2, v3);
                else { p[0] = v2; p[1] = v3; }
            }
        }
    }
}

// ---------------- driver -----------------------------------------------------
extern "C" void kernel_launch(void* const* d_in, const int* in_sizes, int n_in,
                              void* d_out, int out_size) {
    const float* x     = (const float*)d_in[0];
    const int*   er    = (const int*)d_in[1];
    const int*   ea    = (const int*)d_in[2];
    const int*   et    = (const int*)d_in[3];
    const float* mlp_w = (const float*)d_in[4];
    const float* mlp_b = (const float*)d_in[5];
    const float* w1    = (const float*)d_in[6];
    const float* root1 = (const float*)d_in[7];
    const float* b1    = (const float*)d_in[8];
    const float* w2    = (const float*)d_in[9];
    const float* root2 = (const float*)d_in[10];
    const float* b2    = (const float*)d_in[11];
    const float* cls_w = (const float*)d_in[12];
    const float* cls_b = (const float*)d_in[13];
    int E = in_sizes[1];
    float* out = (float*)d_out;

    void *pH0, *pH1, *pS2, *pO2, *pY1, *pOff1, *pOff2, *pBs1, *pBs2, *pCnt1, *pCnt2, *pCur1, *pCur2;
    cudaGetSymbolAddress(&pH0, g_h0);
    cudaGetSymbolAddress(&pH1, g_h1);
    cudaGetSymbolAddress(&pY1, g_y1);
    cudaGetSymbolAddress(&pS2, g_sum2);
    cudaGetSymbolAddress(&pO2, g_out2);
    cudaGetSymbolAddress(&pCnt1, g_cnt1);
    cudaGetSymbolAddress(&pCnt2, g_cnt2);
    cudaGetSymbolAddress(&pOff1, g_off1);
    cudaGetSymbolAddress(&pOff2, g_off2);
    cudaGetSymbolAddress(&pCur1, g_cur1);
    cudaGetSymbolAddress(&pCur2, g_cur2);
    cudaGetSymbolAddress(&pBs1, g_bsum1);
    cudaGetSymbolAddress(&pBs2, g_bsum2);

    cudaFuncSetAttribute(bmma_k, cudaFuncAttributeMaxDynamicSharedMemorySize, MMA_SMEM);

    // --- CSR construction ---
    zero_cnt_k<<<(B1 + 255) / 256, 256>>>();
    count_k<<<(E + 255) / 256, 256>>>(er, ea, et, E);
    scan_blk_k<<<NB1, 1024>>>((const int*)pCnt1, B1, (int*)pOff1, (int*)pBs1);
    scan_blk_k<<<NB2, 1024>>>((const int*)pCnt2, B2, (int*)pOff2, (int*)pBs2);
    scan_top_k<<<1, 1024>>>((int*)pBs1, NB1);
    scan_top_k<<<1, 1024>>>((int*)pBs2, NB2);
    scan_add_k<<<(B1 + 255) / 256, 256>>>((int*)pOff1, (const int*)pBs1, (int*)pCur1, B1);
    scan_add_k<<<(B2 + 255) / 256, 256>>>((int*)pOff2, (const int*)pBs2, (int*)pCur2, B2);
    place_k<<<(E + 255) / 256, 256>>>(er, ea, et, E);

    // --- dense front ---
    mlp_k<<<(NREPO * HDIM + 255) / 256, 256>>>(x, mlp_w, mlp_b);
    uroot_k<<<1, HDIM>>>(mlp_b, root1);

    const int GB = (NREPO + 127) / 128;   // 235
    // y1[repo,r] = h0 @ W1[r]
    bmma_k<<<dim3(GB, 1, RREL), 256, MMA_SMEM>>>(
        (const float*)pH0, NREPO, HDIM, 0, w1, (long)HDIM * HDIM,
        (float*)pY1, RREL * HDIM, HDIM, 0, nullptr);
    // h1[repo] = relu(h0 @ root1 + b1)
    bmma_k<<<dim3(GB, 1, 1), 256, MMA_SMEM>>>(
        (const float*)pH0, NREPO, HDIM, 0, root1, 0,
        (float*)pH1, HDIM, 0, 1, b1);

    // layer-1 aggregation (actor rows of h1)
    agg1_k<<<(NUSER + 7) / 8, 256>>>(b1);

    // layer-2 aggregation
    agg2_k<<<(NREPO + 7) / 8, 256>>>();

    // out2 = h1[:NREPO] @ root2
    bmma_k<<<dim3(GB, 1, 1), 256, MMA_SMEM>>>(
        (const float*)pH1, NREPO, HDIM, 0, root2, 0,
        (float*)pO2, HDIM, 0, 0, nullptr);
    // out2 += mean2 @ w2   (K split over z, red.add epilogue)
    bmma_k<<<dim3(GB, 1, RREL), 256, MMA_SMEM>>>(
        (const float*)pS2, NREPO, RREL * HDIM, HDIM, w2, (long)HDIM * HDIM,
        (float*)pO2, HDIM, 0, 2, nullptr);

    // relu + bias + classifier
    fincls_k<<<NREPO, HDIM>>>(b2, cls_w, cls_b, out);
}

// round 6
// speedup vs baseline: 1.9145x; 1.1617x over previous
#include <cuda_runtime.h>
#include <cuda_bf16.h>
#include <cuda_fp16.h>
#include <cstdint>

#define NREPO 30000
#define NUSER 70000
#define NNODE 100000
#define RREL  8
#define HDIM  128
#define B1 (NUSER * RREL)
#define B2 (NREPO * RREL)
#define NB1 ((B1 + 1023) / 1024)
#define NB2 ((B2 + 1023) / 1024)
#define EMAX 1000000

// ---------------- scratch ----------------------------------------------------
__device__ float  g_h0[(size_t)NREPO * HDIM];
__device__ float  g_h1[(size_t)NNODE * HDIM];
__device__ __half g_y1h[(size_t)B2 * HDIM];          // fp16 y1 (61 MB, L2-resident)
__device__ float  g_sum2[(size_t)B2 * HDIM];
__device__ float  g_uroot[HDIM];
__device__ int    g_cnt1[B1], g_off1[B1], g_cur1[B1], g_bsum1[NB1];
__device__ int    g_cnt2[B2], g_off2[B2], g_cur2[B2], g_bsum2[NB2];
__device__ int    g_perm1[EMAX];   // packed repo*8+r, bucketed by (actor,r)
__device__ int    g_perm2[EMAX];   // actor, bucketed by (repo,r)

// ---------------- counting / CSR build ---------------------------------------
__global__ void zero_cnt_k() {
    int i = blockIdx.x * blockDim.x + threadIdx.x;
    if (i < B1) g_cnt1[i] = 0;
    if (i < B2) g_cnt2[i] = 0;
}

__global__ void count_k(const int* __restrict__ er, const int* __restrict__ ea,
                        const int* __restrict__ et, int E) {
    int e = blockIdx.x * blockDim.x + threadIdx.x;
    if (e >= E) return;
    atomicAdd(&g_cnt1[ea[e] * RREL + et[e]], 1);
    atomicAdd(&g_cnt2[er[e] * RREL + et[e]], 1);
}

__global__ void scan_blk_k(const int* __restrict__ cnt, int n, int* __restrict__ off,
                           int* __restrict__ bsum) {
    __shared__ int s[1024];
    int t = threadIdx.x;
    int i = blockIdx.x * 1024 + t;
    int v = (i < n) ? cnt[i] : 0;
    s[t] = v;
    __syncthreads();
#pragma unroll
    for (int d = 1; d < 1024; d <<= 1) {
        int u = (t >= d) ? s[t - d] : 0;
        __syncthreads();
        s[t] += u;
        __syncthreads();
    }
    if (i < n) off[i] = s[t] - v;
    if (t == 1023) bsum[blockIdx.x] = s[1023];
}

__global__ void scan_top_k(int* __restrict__ bsum, int n) {
    __shared__ int s[1024];
    int t = threadIdx.x;
    int v = (t < n) ? bsum[t] : 0;
    s[t] = v;
    __syncthreads();
#pragma unroll
    for (int d = 1; d < 1024; d <<= 1) {
        int u = (t >= d) ? s[t - d] : 0;
        __syncthreads();
        s[t] += u;
        __syncthreads();
    }
    if (t < n) bsum[t] = s[t] - v;
}

__global__ void scan_add_k(int* __restrict__ off, const int* __restrict__ bsum,
                           int* __restrict__ cur, int n) {
    int i = blockIdx.x * blockDim.x + threadIdx.x;
    if (i >= n) return;
    int o = off[i] + bsum[i >> 10];
    off[i] = o;
    cur[i] = o;
}

__global__ void place_k(const int* __restrict__ er, const int* __restrict__ ea,
                        const int* __restrict__ et, int E) {
    int e = blockIdx.x * blockDim.x + threadIdx.x;
    if (e >= E) return;
    int repo = er[e], actor = ea[e], t = et[e];
    int p1 = atomicAdd(&g_cur1[actor * RREL + t], 1);
    g_perm1[p1] = repo * RREL + t;             // packed: directly indexes y1 rows
    int p2 = atomicAdd(&g_cur2[repo * RREL + t], 1);
    g_perm2[p2] = actor;
}

// ---------------- dense small pieces -----------------------------------------
__global__ void mlp_k(const float* __restrict__ x, const float* __restrict__ w,
                      const float* __restrict__ b) {
    int g = blockIdx.x * blockDim.x + threadIdx.x;
    if (g >= NREPO * HDIM) return;
    int n = g >> 7, o = g & 127;
    float acc = b[o];
#pragma unroll
    for (int k = 0; k < 8; k++) acc = fmaf(__ldg(&x[n * 8 + k]), __ldg(&w[k * HDIM + o]), acc);
    g_h0[g] = fmaxf(acc, 0.f);
}

__global__ void uroot_k(const float* __restrict__ mlp_b, const float* __restrict__ root1) {
    int o = threadIdx.x;
    float acc = 0.f;
#pragma unroll 8
    for (int k = 0; k < HDIM; k++)
        acc = fmaf(fmaxf(mlp_b[k], 0.f), root1[k * HDIM + o], acc);
    g_uroot[o] = acc;
}

// layer-1 aggregation: one warp per actor, flat edge loop (perm1 packed repo*8+r)
__global__ void agg1_k(const float* __restrict__ b1, int E) {
    int w = (blockIdx.x * blockDim.x + threadIdx.x) >> 5;
    int lane = threadIdx.x & 31;
    if (w >= NUSER) return;
    float inv[RREL];
#pragma unroll
    for (int r = 0; r < RREL; r++) {
        int d = g_cnt1[w * RREL + r];
        inv[r] = d ? 1.0f / (float)d : 0.f;
    }
    int start = g_off1[w * RREL];
    int end = (w * RREL + RREL < B1) ? g_off1[w * RREL + RREL] : E;
    float4 acc = *(const float4*)(g_uroot + lane * 4);

    int j = start;
    for (; j + 4 <= end; j += 4) {
        int p0 = __ldg(g_perm1 + j),     p1 = __ldg(g_perm1 + j + 1);
        int p2 = __ldg(g_perm1 + j + 2), p3 = __ldg(g_perm1 + j + 3);
        uint2 u0 = *(const uint2*)(g_y1h + (((size_t)p0) << 7) + lane * 4);
        uint2 u1 = *(const uint2*)(g_y1h + (((size_t)p1) << 7) + lane * 4);
        uint2 u2 = *(const uint2*)(g_y1h + (((size_t)p2) << 7) + lane * 4);
        uint2 u3 = *(const uint2*)(g_y1h + (((size_t)p3) << 7) + lane * 4);
        float iv0 = inv[p0 & 7], iv1 = inv[p1 & 7], iv2 = inv[p2 & 7], iv3 = inv[p3 & 7];
#define ACC1(u, iv) { \
        float2 lo = __half22float2(((const __half2*)&(u))[0]); \
        float2 hi = __half22float2(((const __half2*)&(u))[1]); \
        acc.x = fmaf(lo.x, (iv), acc.x); acc.y = fmaf(lo.y, (iv), acc.y); \
        acc.z = fmaf(hi.x, (iv), acc.z); acc.w = fmaf(hi.y, (iv), acc.w); }
        ACC1(u0, iv0) ACC1(u1, iv1) ACC1(u2, iv2) ACC1(u3, iv3)
    }
    for (; j < end; j++) {
        int p0 = __ldg(g_perm1 + j);
        uint2 u0 = *(const uint2*)(g_y1h + (((size_t)p0) << 7) + lane * 4);
        float iv0 = inv[p0 & 7];
        ACC1(u0, iv0)
    }
#undef ACC1
    const float4 bb = *(const float4*)(b1 + lane * 4);
    acc.x = fmaxf(acc.x + bb.x, 0.f); acc.y = fmaxf(acc.y + bb.y, 0.f);
    acc.z = fmaxf(acc.z + bb.z, 0.f); acc.w = fmaxf(acc.w + bb.w, 0.f);
    *(float4*)(g_h1 + (((size_t)(NREPO + w)) << 7) + lane * 4) = acc;
}

// layer-2 aggregation: one warp per (repo, relation) bin
__global__ void agg2_k() {
    int bin = (blockIdx.x * blockDim.x + threadIdx.x) >> 5;
    int lane = threadIdx.x & 31;
    if (bin >= B2) return;
    int deg = g_cnt2[bin];
    int start = g_off2[bin];
    float4 s = make_float4(0.f, 0.f, 0.f, 0.f);
    int j = 0;
    for (; j + 2 <= deg; j += 2) {
        int a0 = __ldg(g_perm2 + start + j);
        int a1 = __ldg(g_perm2 + start + j + 1);
        const float4 v0 = *(const float4*)(g_h1 + (((size_t)(NREPO + a0)) << 7) + lane * 4);
        const float4 v1 = *(const float4*)(g_h1 + (((size_t)(NREPO + a1)) << 7) + lane * 4);
        s.x += v0.x + v1.x; s.y += v0.y + v1.y; s.z += v0.z + v1.z; s.w += v0.w + v1.w;
    }
    if (j < deg) {
        int a0 = __ldg(g_perm2 + start + j);
        const float4 v0 = *(const float4*)(g_h1 + (((size_t)(NREPO + a0)) << 7) + lane * 4);
        s.x += v0.x; s.y += v0.y; s.z += v0.z; s.w += v0.w;
    }
    float inv = deg ? 1.0f / (float)deg : 0.f;
    s.x *= inv; s.y *= inv; s.z *= inv; s.w *= inv;
    *(float4*)(g_sum2 + ((size_t)bin << 7) + lane * 4) = s;
}

// ================= bf16 3-term tensor-core GEMM pieces =======================
#define PITCH 136
#define AH_OFF 0
#define AL_OFF 34816
#define BH_OFF 69632
#define BL_OFF 104448
#define MMA_SMEM 139264

__device__ __forceinline__ uint32_t smem_u32(const void* p) {
    uint32_t a;
    asm("{ .reg .u64 t; cvta.to.shared.u64 t, %1; cvt.u32.u64 %0, t; }" : "=r"(a) : "l"(p));
    return a;
}

__device__ __forceinline__ void ldsm_x4(unsigned r[4], uint32_t addr) {
    asm volatile("ldmatrix.sync.aligned.m8n8.x4.shared.b16 {%0,%1,%2,%3}, [%4];"
                 : "=r"(r[0]), "=r"(r[1]), "=r"(r[2]), "=r"(r[3]) : "r"(addr));
}

__device__ __forceinline__ void ldsm_x4_t(unsigned r[4], uint32_t addr) {
    asm volatile("ldmatrix.sync.aligned.m8n8.x4.trans.shared.b16 {%0,%1,%2,%3}, [%4];"
                 : "=r"(r[0]), "=r"(r[1]), "=r"(r[2]), "=r"(r[3]) : "r"(addr));
}

__device__ __forceinline__ void mma_bf16(float c[4], const unsigned a[4], const unsigned* b) {
    asm volatile(
        "mma.sync.aligned.m16n8k16.row.col.f32.bf16.bf16.f32 "
        "{%0,%1,%2,%3}, {%4,%5,%6,%7}, {%8,%9}, {%0,%1,%2,%3};"
        : "+f"(c[0]), "+f"(c[1]), "+f"(c[2]), "+f"(c[3])
        : "r"(a[0]), "r"(a[1]), "r"(a[2]), "r"(a[3]), "r"(b[0]), "r"(b[1]));
}

__device__ __forceinline__ void sp_bf(float x, unsigned short& h, unsigned short& l) {
    __nv_bfloat16 hb = __float2bfloat16_rn(x);
    h = __bfloat16_as_ushort(hb);
    l = __bfloat16_as_ushort(__float2bfloat16_rn(x - __bfloat162float(hb)));
}

// load A[m0.., lda, +cO] and B[128x128] tiles, split to bf16 hi/lo planes
__device__ __forceinline__ void load_split(char* sm, const float* __restrict__ A, int lda,
                                           int cO, const float* __restrict__ B,
                                           int m0, int M, int tid) {
#pragma unroll
    for (int it = 0; it < 16; it++) {
        int v = tid + it * 256;
        int row = v >> 5;
        int c4 = (v & 31) * 4;
        float4 fa = (m0 + row < M) ? *(const float4*)(A + (size_t)(m0 + row) * lda + cO + c4)
                                   : make_float4(0.f, 0.f, 0.f, 0.f);
        unsigned short h0, h1, h2, h3, l0, l1, l2, l3;
        sp_bf(fa.x, h0, l0); sp_bf(fa.y, h1, l1); sp_bf(fa.z, h2, l2); sp_bf(fa.w, h3, l3);
        int off = (row * PITCH + c4) * 2;
        *(uint2*)(sm + AH_OFF + off) = make_uint2((unsigned)h0 | ((unsigned)h1 << 16),
                                                  (unsigned)h2 | ((unsigned)h3 << 16));
        *(uint2*)(sm + AL_OFF + off) = make_uint2((unsigned)l0 | ((unsigned)l1 << 16),
                                                  (unsigned)l2 | ((unsigned)l3 << 16));
        float4 fb = *(const float4*)(B + (size_t)row * 128 + c4);
        sp_bf(fb.x, h0, l0); sp_bf(fb.y, h1, l1); sp_bf(fb.z, h2, l2); sp_bf(fb.w, h3, l3);
        *(uint2*)(sm + BH_OFF + off) = make_uint2((unsigned)h0 | ((unsigned)h1 << 16),
                                                  (unsigned)h2 | ((unsigned)h3 << 16));
        *(uint2*)(sm + BL_OFF + off) = make_uint2((unsigned)l0 | ((unsigned)l1 << 16),
                                                  (unsigned)l2 | ((unsigned)l3 << 16));
    }
}

// 8 k-chunks of ldmatrix + 3-term mma over the planes
__device__ __forceinline__ void compute_planes(uint32_t sb, int wm, int wn, int lrow,
                                               int lhalf, float (&acc)[4][4][4]) {
#pragma unroll 1
    for (int kc = 0; kc < 8; kc++) {
        int k0 = kc * 16;
        unsigned Ah[4][4], Al[4][4], Bh[2][4], Bl[2][4];
#pragma unroll
        for (int mf = 0; mf < 4; mf++) {
            uint32_t a = sb + ((wm + mf * 16 + lrow) * PITCH + k0 + lhalf) * 2;
            ldsm_x4(Ah[mf], a + AH_OFF);
            ldsm_x4(Al[mf], a + AL_OFF);
        }
#pragma unroll
        for (int np = 0; np < 2; np++) {
            uint32_t a = sb + ((k0 + lrow) * PITCH + wn + np * 16 + lhalf) * 2;
            ldsm_x4_t(Bh[np], a + BH_OFF);
            ldsm_x4_t(Bl[np], a + BL_OFF);
        }
#pragma unroll
        for (int mf = 0; mf < 4; mf++)
#pragma unroll
            for (int nf = 0; nf < 4; nf++) {
                const unsigned* bh = &Bh[nf >> 1][(nf & 1) * 2];
                const unsigned* bl = &Bl[nf >> 1][(nf & 1) * 2];
                mma_bf16(acc[mf][nf], Ah[mf], bh);
                mma_bf16(acc[mf][nf], Al[mf], bh);
                mma_bf16(acc[mf][nf], Ah[mf], bl);
            }
    }
}

// bmma: C = A[Mx128] @ B[z][128x128]. mode 1: fp32 store relu(acc+bias); mode 3: fp16 store.
__global__ void __launch_bounds__(256)
bmma_k(const float* __restrict__ A, int M,
       const float* __restrict__ B, long bStrideZ,
       void* __restrict__ Cv, int cstride, int cOffZ, int mode,
       const float* __restrict__ bias) {
    extern __shared__ char sm[];
    const uint32_t sb = smem_u32(sm);
    const int tid = threadIdx.x;
    const int lane = tid & 31;
    const int warp = tid >> 5;
    const int wm = (warp >> 2) * 64;
    const int wn = (warp & 3) * 32;
    const int z = blockIdx.z;
    const float* Bb = B + (size_t)z * bStrideZ;
    const int cOff = z * cOffZ;
    const int m0 = blockIdx.x * 128;

    load_split(sm, A, HDIM, 0, Bb, m0, M, tid);
    __syncthreads();

    float acc[4][4][4];
#pragma unroll
    for (int i = 0; i < 4; i++)
#pragma unroll
        for (int j = 0; j < 4; j++)
#pragma unroll
            for (int k = 0; k < 4; k++) acc[i][j][k] = 0.f;

    const int lrow = lane & 15;
    const int lhalf = (lane >> 4) * 8;
    compute_planes(sb, wm, wn, lrow, lhalf, acc);

#pragma unroll
    for (int mf = 0; mf < 4; mf++) {
#pragma unroll
        for (int nf = 0; nf < 4; nf++) {
            int r0 = m0 + wm + mf * 16 + (lane >> 2);
            int r1 = r0 + 8;
            int cl = wn + nf * 8 + (lane & 3) * 2;
            float v0 = acc[mf][nf][0], v1 = acc[mf][nf][1];
            float v2 = acc[mf][nf][2], v3 = acc[mf][nf][3];
            if (mode == 1) {
                float b0 = bias[cl], b1v = bias[cl + 1];
                v0 = fmaxf(v0 + b0, 0.f); v1 = fmaxf(v1 + b1v, 0.f);
                v2 = fmaxf(v2 + b0, 0.f); v3 = fmaxf(v3 + b1v, 0.f);
                float* C = (float*)Cv;
                if (r0 < M) { float* p = C + (size_t)r0 * cstride + cOff + cl; p[0] = v0; p[1] = v1; }
                if (r1 < M) { float* p = C + (size_t)r1 * cstride + cOff + cl; p[0] = v2; p[1] = v3; }
            } else {  // mode 3: fp16
                __half* C = (__half*)Cv;
                if (r0 < M) *(__half2*)(C + (size_t)r0 * cstride + cOff + cl) = __floats2half2_rn(v0, v1);
                if (r1 < M) *(__half2*)(C + (size_t)r1 * cstride + cOff + cl) = __floats2half2_rn(v2, v3);
            }
        }
    }
}

// fused layer-2: out2 = mean2 @ w2 (8 slabs) + h1 @ root2 (1 slab),
// then relu(+b2), classifier (cls_w [128,2], cls_b), write out[M,2].
__global__ void __launch_bounds__(256)
l2_k(const float* __restrict__ sum2, const float* __restrict__ h1,
     const float* __restrict__ w2, const float* __restrict__ root2,
     const float* __restrict__ b2, const float* __restrict__ clsw,
     const float* __restrict__ clsb, float* __restrict__ out, int M) {
    extern __shared__ char sm[];
    const uint32_t sb = smem_u32(sm);
    const int tid = threadIdx.x;
    const int lane = tid & 31;
    const int warp = tid >> 5;
    const int wm = (warp >> 2) * 64;
    const int wn = (warp & 3) * 32;
    const int m0 = blockIdx.x * 128;
    const int lrow = lane & 15;
    const int lhalf = (lane >> 4) * 8;

    float acc[4][4][4];
#pragma unroll
    for (int i = 0; i < 4; i++)
#pragma unroll
        for (int j = 0; j < 4; j++)
#pragma unroll
            for (int k = 0; k < 4; k++) acc[i][j][k] = 0.f;

#pragma unroll 1
    for (int s = 0; s < 9; s++) {
        const float* Asrc = (s < 8) ? sum2 : h1;
        int lda  = (s < 8) ? RREL * HDIM : HDIM;
        int cO   = (s < 8) ? s * HDIM : 0;
        const float* Bsrc = (s < 8) ? (w2 + (size_t)s * HDIM * HDIM) : root2;
        load_split(sm, Asrc, lda, cO, Bsrc, m0, M, tid);
        __syncthreads();
        compute_planes(sb, wm, wn, lrow, lhalf, acc);
        __syncthreads();
    }

    // classifier epilogue (smem planes reused as reduction buffers)
    float* redA = (float*)sm;          // [128][4] channel 0
    float* redB = (float*)sm + 512;    // [128][4] channel 1
#pragma unroll
    for (int mf = 0; mf < 4; mf++) {
        float p0a = 0.f, p0b = 0.f, p1a = 0.f, p1b = 0.f;
#pragma unroll
        for (int nf = 0; nf < 4; nf++) {
            int cl = wn + nf * 8 + (lane & 3) * 2;
            float b0 = b2[cl], b1v = b2[cl + 1];
            float w00 = clsw[cl * 2], w01 = clsw[cl * 2 + 1];
            float w10 = clsw[(cl + 1) * 2], w11 = clsw[(cl + 1) * 2 + 1];
            float v0 = fmaxf(acc[mf][nf][0] + b0, 0.f);
            float v1 = fmaxf(acc[mf][nf][1] + b1v, 0.f);
            float v2 = fmaxf(acc[mf][nf][2] + b0, 0.f);
            float v3 = fmaxf(acc[mf][nf][3] + b1v, 0.f);
            p0a += v0 * w00 + v1 * w10; p0b += v0 * w01 + v1 * w11;
            p1a += v2 * w00 + v3 * w10; p1b += v2 * w01 + v3 * w11;
        }
#pragma unroll
        for (int o = 1; o <= 2; o <<= 1) {
            p0a += __shfl_xor_sync(0xffffffffu, p0a, o);
            p0b += __shfl_xor_sync(0xffffffffu, p0b, o);
            p1a += __shfl_xor_sync(0xffffffffu, p1a, o);
            p1b += __shfl_xor_sync(0xffffffffu, p1b, o);
        }
        if ((lane & 3) == 0) {
            int r0 = wm + mf * 16 + (lane >> 2);
            redA[r0 * 4 + (warp & 3)] = p0a;
            redB[r0 * 4 + (warp & 3)] = p0b;
            redA[(r0 + 8) * 4 + (warp & 3)] = p1a;
            redB[(r0 + 8) * 4 + (warp & 3)] = p1b;
        }
    }
    __syncthreads();
    if (tid < 128) {
        int gr = m0 + tid;
        if (gr < M) {
            float o0 = redA[tid * 4] + redA[tid * 4 + 1] + redA[tid * 4 + 2] + redA[tid * 4 + 3] + clsb[0];
            float o1 = redB[tid * 4] + redB[tid * 4 + 1] + redB[tid * 4 + 2] + redB[tid * 4 + 3] + clsb[1];
            out[gr * 2 + 0] = o0;
            out[gr * 2 + 1] = o1;
        }
    }
}

// ---------------- driver -----------------------------------------------------
extern "C" void kernel_launch(void* const* d_in, const int* in_sizes, int n_in,
                              void* d_out, int out_size) {
    const float* x     = (const float*)d_in[0];
    const int*   er    = (const int*)d_in[1];
    const int*   ea    = (const int*)d_in[2];
    const int*   et    = (const int*)d_in[3];
    const float* mlp_w = (const float*)d_in[4];
    const float* mlp_b = (const float*)d_in[5];
    const float* w1    = (const float*)d_in[6];
    const float* root1 = (const float*)d_in[7];
    const float* b1    = (const float*)d_in[8];
    const float* w2    = (const float*)d_in[9];
    const float* root2 = (const float*)d_in[10];
    const float* b2    = (const float*)d_in[11];
    const float* cls_w = (const float*)d_in[12];
    const float* cls_b = (const float*)d_in[13];
    int E = in_sizes[1];
    float* out = (float*)d_out;

    void *pH0, *pH1, *pS2, *pY1h, *pOff1, *pOff2, *pBs1, *pBs2, *pCnt1, *pCnt2, *pCur1, *pCur2;
    cudaGetSymbolAddress(&pH0, g_h0);
    cudaGetSymbolAddress(&pH1, g_h1);
    cudaGetSymbolAddress(&pY1h, g_y1h);
    cudaGetSymbolAddress(&pS2, g_sum2);
    cudaGetSymbolAddress(&pCnt1, g_cnt1);
    cudaGetSymbolAddress(&pCnt2, g_cnt2);
    cudaGetSymbolAddress(&pOff1, g_off1);
    cudaGetSymbolAddress(&pOff2, g_off2);
    cudaGetSymbolAddress(&pCur1, g_cur1);
    cudaGetSymbolAddress(&pCur2, g_cur2);
    cudaGetSymbolAddress(&pBs1, g_bsum1);
    cudaGetSymbolAddress(&pBs2, g_bsum2);

    cudaFuncSetAttribute(bmma_k, cudaFuncAttributeMaxDynamicSharedMemorySize, MMA_SMEM);
    cudaFuncSetAttribute(l2_k, cudaFuncAttributeMaxDynamicSharedMemorySize, MMA_SMEM);

    // --- CSR construction ---
    zero_cnt_k<<<(B1 + 255) / 256, 256>>>();
    count_k<<<(E + 255) / 256, 256>>>(er, ea, et, E);
    scan_blk_k<<<NB1, 1024>>>((const int*)pCnt1, B1, (int*)pOff1, (int*)pBs1);
    scan_blk_k<<<NB2, 1024>>>((const int*)pCnt2, B2, (int*)pOff2, (int*)pBs2);
    scan_top_k<<<1, 1024>>>((int*)pBs1, NB1);
    scan_top_k<<<1, 1024>>>((int*)pBs2, NB2);
    scan_add_k<<<(B1 + 255) / 256, 256>>>((int*)pOff1, (const int*)pBs1, (int*)pCur1, B1);
    scan_add_k<<<(B2 + 255) / 256, 256>>>((int*)pOff2, (const int*)pBs2, (int*)pCur2, B2);
    place_k<<<(E + 255) / 256, 256>>>(er, ea, et, E);

    // --- dense front ---
    mlp_k<<<(NREPO * HDIM + 255) / 256, 256>>>(x, mlp_w, mlp_b);
    uroot_k<<<1, HDIM>>>(mlp_b, root1);

    const int GB = (NREPO + 127) / 128;   // 235
    // y1[repo,r] = h0 @ W1[r]  -> fp16
    bmma_k<<<dim3(GB, 1, RREL), 256, MMA_SMEM>>>(
        (const float*)pH0, NREPO, w1, (long)HDIM * HDIM,
        pY1h, RREL * HDIM, HDIM, 3, nullptr);
    // h1[repo] = relu(h0 @ root1 + b1)
    bmma_k<<<dim3(GB, 1, 1), 256, MMA_SMEM>>>(
        (const float*)pH0, NREPO, root1, 0,
        pH1, HDIM, 0, 1, b1);

    // layer-1 aggregation (actor rows of h1)
    agg1_k<<<(NUSER * 32 + 255) / 256, 256>>>(b1, E);

    // layer-2 aggregation -> per-(repo,r) means (warp per bin)
    agg2_k<<<(B2 * 32 + 255) / 256, 256>>>();

    // fused layer-2 dense + classifier
    l2_k<<<GB, 256, MMA_SMEM>>>(
        (const float*)pS2, (const float*)pH1, w2, root2, b2, cls_w, cls_b, out, NREPO);
}

// round 7
// speedup vs baseline: 1.9633x; 1.0255x over previous
#include <cuda_runtime.h>
#include <cuda_bf16.h>
#include <cuda_fp16.h>
#include <cstdint>

#define NREPO 30000
#define NUSER 70000
#define NNODE 100000
#define RREL  8
#define HDIM  128
#define B1 (NUSER * RREL)
#define B2 (NREPO * RREL)
#define NB1 ((B1 + 1023) / 1024)
#define NB2 ((B2 + 1023) / 1024)
#define EMAX 1000000

// ---------------- scratch ----------------------------------------------------
__device__ float  g_h0[(size_t)NREPO * HDIM];
__device__ __half g_h1h[(size_t)NNODE * HDIM];       // fp16 h1 (26 MB)
__device__ __half g_y1h[(size_t)B2 * HDIM];          // fp16 y1 (61 MB)
__device__ __half g_sum2h[(size_t)B2 * HDIM];        // fp16 layer-2 means (61 MB)
__device__ float  g_uroot[HDIM];
__device__ int    g_cnt1[B1], g_off1[B1], g_cur1[B1], g_bsum1[NB1];
__device__ int    g_cnt2[B2], g_off2[B2], g_cur2[B2], g_bsum2[NB2];
__device__ int    g_perm1[EMAX];   // packed repo*8+r, bucketed by (actor,r)
__device__ int    g_perm2[EMAX];   // actor, bucketed by (repo,r)

// ---------------- counting / CSR build ---------------------------------------
__global__ void zero_cnt_k() {
    int i = blockIdx.x * blockDim.x + threadIdx.x;
    if (i < B1) g_cnt1[i] = 0;
    if (i < B2) g_cnt2[i] = 0;
}

__global__ void count_k(const int* __restrict__ er, const int* __restrict__ ea,
                        const int* __restrict__ et, int E) {
    int e = blockIdx.x * blockDim.x + threadIdx.x;
    if (e >= E) return;
    atomicAdd(&g_cnt1[ea[e] * RREL + et[e]], 1);
    atomicAdd(&g_cnt2[er[e] * RREL + et[e]], 1);
}

__global__ void scan_blk_k(const int* __restrict__ cnt, int n, int* __restrict__ off,
                           int* __restrict__ bsum) {
    __shared__ int s[1024];
    int t = threadIdx.x;
    int i = blockIdx.x * 1024 + t;
    int v = (i < n) ? cnt[i] : 0;
    s[t] = v;
    __syncthreads();
#pragma unroll
    for (int d = 1; d < 1024; d <<= 1) {
        int u = (t >= d) ? s[t - d] : 0;
        __syncthreads();
        s[t] += u;
        __syncthreads();
    }
    if (i < n) off[i] = s[t] - v;
    if (t == 1023) bsum[blockIdx.x] = s[1023];
}

__global__ void scan_top_k(int* __restrict__ bsum, int n) {
    __shared__ int s[1024];
    int t = threadIdx.x;
    int v = (t < n) ? bsum[t] : 0;
    s[t] = v;
    __syncthreads();
#pragma unroll
    for (int d = 1; d < 1024; d <<= 1) {
        int u = (t >= d) ? s[t - d] : 0;
        __syncthreads();
        s[t] += u;
        __syncthreads();
    }
    if (t < n) bsum[t] = s[t] - v;
}

__global__ void scan_add_k(int* __restrict__ off, const int* __restrict__ bsum,
                           int* __restrict__ cur, int n) {
    int i = blockIdx.x * blockDim.x + threadIdx.x;
    if (i >= n) return;
    int o = off[i] + bsum[i >> 10];
    off[i] = o;
    cur[i] = o;
}

__global__ void place_k(const int* __restrict__ er, const int* __restrict__ ea,
                        const int* __restrict__ et, int E) {
    int e = blockIdx.x * blockDim.x + threadIdx.x;
    if (e >= E) return;
    int repo = er[e], actor = ea[e], t = et[e];
    int p1 = atomicAdd(&g_cur1[actor * RREL + t], 1);
    g_perm1[p1] = repo * RREL + t;
    int p2 = atomicAdd(&g_cur2[repo * RREL + t], 1);
    g_perm2[p2] = actor;
}

// ---------------- dense small pieces -----------------------------------------
__global__ void mlp_k(const float* __restrict__ x, const float* __restrict__ w,
                      const float* __restrict__ b) {
    int g = blockIdx.x * blockDim.x + threadIdx.x;
    if (g >= NREPO * HDIM) return;
    int n = g >> 7, o = g & 127;
    float acc = b[o];
#pragma unroll
    for (int k = 0; k < 8; k++) acc = fmaf(__ldg(&x[n * 8 + k]), __ldg(&w[k * HDIM + o]), acc);
    g_h0[g] = fmaxf(acc, 0.f);
}

__global__ void uroot_k(const float* __restrict__ mlp_b, const float* __restrict__ root1) {
    int o = threadIdx.x;
    float acc = 0.f;
#pragma unroll 8
    for (int k = 0; k < HDIM; k++)
        acc = fmaf(fmaxf(mlp_b[k], 0.f), root1[k * HDIM + o], acc);
    g_uroot[o] = acc;
}

// layer-1 aggregation: one warp per actor, flat edge loop, fp16 in / fp16 out
__global__ void agg1_k(const float* __restrict__ b1, int E) {
    int w = (blockIdx.x * blockDim.x + threadIdx.x) >> 5;
    int lane = threadIdx.x & 31;
    if (w >= NUSER) return;
    float inv[RREL];
#pragma unroll
    for (int r = 0; r < RREL; r++) {
        int d = g_cnt1[w * RREL + r];
        inv[r] = d ? 1.0f / (float)d : 0.f;
    }
    int start = g_off1[w * RREL];
    int end = (w * RREL + RREL < B1) ? g_off1[w * RREL + RREL] : E;
    float4 acc = *(const float4*)(g_uroot + lane * 4);

    int j = start;
    for (; j + 4 <= end; j += 4) {
        int p0 = __ldg(g_perm1 + j),     p1 = __ldg(g_perm1 + j + 1);
        int p2 = __ldg(g_perm1 + j + 2), p3 = __ldg(g_perm1 + j + 3);
        uint2 u0 = *(const uint2*)(g_y1h + (((size_t)p0) << 7) + lane * 4);
        uint2 u1 = *(const uint2*)(g_y1h + (((size_t)p1) << 7) + lane * 4);
        uint2 u2 = *(const uint2*)(g_y1h + (((size_t)p2) << 7) + lane * 4);
        uint2 u3 = *(const uint2*)(g_y1h + (((size_t)p3) << 7) + lane * 4);
        float iv0 = inv[p0 & 7], iv1 = inv[p1 & 7], iv2 = inv[p2 & 7], iv3 = inv[p3 & 7];
#define ACC1(u, iv) { \
        float2 lo = __half22float2(((const __half2*)&(u))[0]); \
        float2 hi = __half22float2(((const __half2*)&(u))[1]); \
        acc.x = fmaf(lo.x, (iv), acc.x); acc.y = fmaf(lo.y, (iv), acc.y); \
        acc.z = fmaf(hi.x, (iv), acc.z); acc.w = fmaf(hi.y, (iv), acc.w); }
        ACC1(u0, iv0) ACC1(u1, iv1) ACC1(u2, iv2) ACC1(u3, iv3)
    }
    for (; j < end; j++) {
        int p0 = __ldg(g_perm1 + j);
        uint2 u0 = *(const uint2*)(g_y1h + (((size_t)p0) << 7) + lane * 4);
        float iv0 = inv[p0 & 7];
        ACC1(u0, iv0)
    }
#undef ACC1
    const float4 bb = *(const float4*)(b1 + lane * 4);
    __half2 o0 = __floats2half2_rn(fmaxf(acc.x + bb.x, 0.f), fmaxf(acc.y + bb.y, 0.f));
    __half2 o1 = __floats2half2_rn(fmaxf(acc.z + bb.z, 0.f), fmaxf(acc.w + bb.w, 0.f));
    uint2 pk;
    pk.x = *(unsigned*)&o0; pk.y = *(unsigned*)&o1;
    *(uint2*)(g_h1h + (((size_t)(NREPO + w)) << 7) + lane * 4) = pk;
}

// layer-2 aggregation: one warp per (repo, relation) bin, fp16 in / fp16 out
__global__ void agg2_k() {
    int bin = (blockIdx.x * blockDim.x + threadIdx.x) >> 5;
    int lane = threadIdx.x & 31;
    if (bin >= B2) return;
    int deg = g_cnt2[bin];
    int start = g_off2[bin];
    float4 s = make_float4(0.f, 0.f, 0.f, 0.f);
#define ACC2(u) { \
        float2 lo = __half22float2(((const __half2*)&(u))[0]); \
        float2 hi = __half22float2(((const __half2*)&(u))[1]); \
        s.x += lo.x; s.y += lo.y; s.z += hi.x; s.w += hi.y; }
    int j = 0;
    for (; j + 2 <= deg; j += 2) {
        int a0 = __ldg(g_perm2 + start + j);
        int a1 = __ldg(g_perm2 + start + j + 1);
        uint2 u0 = *(const uint2*)(g_h1h + (((size_t)(NREPO + a0)) << 7) + lane * 4);
        uint2 u1 = *(const uint2*)(g_h1h + (((size_t)(NREPO + a1)) << 7) + lane * 4);
        ACC2(u0) ACC2(u1)
    }
    if (j < deg) {
        int a0 = __ldg(g_perm2 + start + j);
        uint2 u0 = *(const uint2*)(g_h1h + (((size_t)(NREPO + a0)) << 7) + lane * 4);
        ACC2(u0)
    }
#undef ACC2
    float inv = deg ? 1.0f / (float)deg : 0.f;
    __half2 o0 = __floats2half2_rn(s.x * inv, s.y * inv);
    __half2 o1 = __floats2half2_rn(s.z * inv, s.w * inv);
    uint2 pk;
    pk.x = *(unsigned*)&o0; pk.y = *(unsigned*)&o1;
    *(uint2*)(g_sum2h + ((size_t)bin << 7) + lane * 4) = pk;
}

// ================= bf16 3-term tensor-core GEMM pieces =======================
#define PITCH 136
#define AH_OFF 0
#define AL_OFF 34816
#define BH_OFF 69632
#define BL_OFF 104448
#define MMA_SMEM 139264

__device__ __forceinline__ uint32_t smem_u32(const void* p) {
    uint32_t a;
    asm("{ .reg .u64 t; cvta.to.shared.u64 t, %1; cvt.u32.u64 %0, t; }" : "=r"(a) : "l"(p));
    return a;
}

__device__ __forceinline__ void ldsm_x4(unsigned r[4], uint32_t addr) {
    asm volatile("ldmatrix.sync.aligned.m8n8.x4.shared.b16 {%0,%1,%2,%3}, [%4];"
                 : "=r"(r[0]), "=r"(r[1]), "=r"(r[2]), "=r"(r[3]) : "r"(addr));
}

__device__ __forceinline__ void ldsm_x4_t(unsigned r[4], uint32_t addr) {
    asm volatile("ldmatrix.sync.aligned.m8n8.x4.trans.shared.b16 {%0,%1,%2,%3}, [%4];"
                 : "=r"(r[0]), "=r"(r[1]), "=r"(r[2]), "=r"(r[3]) : "r"(addr));
}

__device__ __forceinline__ void mma_bf16(float c[4], const unsigned a[4], const unsigned* b) {
    asm volatile(
        "mma.sync.aligned.m16n8k16.row.col.f32.bf16.bf16.f32 "
        "{%0,%1,%2,%3}, {%4,%5,%6,%7}, {%8,%9}, {%0,%1,%2,%3};"
        : "+f"(c[0]), "+f"(c[1]), "+f"(c[2]), "+f"(c[3])
        : "r"(a[0]), "r"(a[1]), "r"(a[2]), "r"(a[3]), "r"(b[0]), "r"(b[1]));
}

__device__ __forceinline__ void sp_bf(float x, unsigned short& h, unsigned short& l) {
    __nv_bfloat16 hb = __float2bfloat16_rn(x);
    h = __bfloat16_as_ushort(hb);
    l = __bfloat16_as_ushort(__float2bfloat16_rn(x - __bfloat162float(hb)));
}

__device__ __forceinline__ void store_planes(char* sm, int plane_off_h, int plane_off_l,
                                             int row, int c4, float4 f) {
    unsigned short h0, h1, h2, h3, l0, l1, l2, l3;
    sp_bf(f.x, h0, l0); sp_bf(f.y, h1, l1); sp_bf(f.z, h2, l2); sp_bf(f.w, h3, l3);
    int off = (row * PITCH + c4) * 2;
    *(uint2*)(sm + plane_off_h + off) = make_uint2((unsigned)h0 | ((unsigned)h1 << 16),
                                                   (unsigned)h2 | ((unsigned)h3 << 16));
    *(uint2*)(sm + plane_off_l + off) = make_uint2((unsigned)l0 | ((unsigned)l1 << 16),
                                                   (unsigned)l2 | ((unsigned)l3 << 16));
}

// A-tile fp32 -> planes
__device__ __forceinline__ void load_A_f32(char* sm, const float* __restrict__ A, int lda,
                                           int m0, int M, int tid) {
#pragma unroll
    for (int it = 0; it < 16; it++) {
        int v = tid + it * 256;
        int row = v >> 5;
        int c4 = (v & 31) * 4;
        float4 fa = (m0 + row < M) ? *(const float4*)(A + (size_t)(m0 + row) * lda + c4)
                                   : make_float4(0.f, 0.f, 0.f, 0.f);
        store_planes(sm, AH_OFF, AL_OFF, row, c4, fa);
    }
}

// A-tile fp16 -> planes (fp16 -> bf16 hi/lo is exact)
__device__ __forceinline__ void load_A_f16(char* sm, const __half* __restrict__ A, int lda,
                                           int cO, int m0, int M, int tid) {
#pragma unroll
    for (int it = 0; it < 16; it++) {
        int v = tid + it * 256;
        int row = v >> 5;
        int c4 = (v & 31) * 4;
        float4 fa = make_float4(0.f, 0.f, 0.f, 0.f);
        if (m0 + row < M) {
            uint2 u = *(const uint2*)(A + (size_t)(m0 + row) * lda + cO + c4);
            float2 lo = __half22float2(((const __half2*)&u)[0]);
            float2 hi = __half22float2(((const __half2*)&u)[1]);
            fa = make_float4(lo.x, lo.y, hi.x, hi.y);
        }
        store_planes(sm, AH_OFF, AL_OFF, row, c4, fa);
    }
}

// B 128x128 fp32 -> planes
__device__ __forceinline__ void load_B_f32(char* sm, const float* __restrict__ B, int tid) {
#pragma unroll
    for (int it = 0; it < 16; it++) {
        int v = tid + it * 256;
        int row = v >> 5;
        int c4 = (v & 31) * 4;
        float4 fb = *(const float4*)(B + (size_t)row * 128 + c4);
        store_planes(sm, BH_OFF, BL_OFF, row, c4, fb);
    }
}

__device__ __forceinline__ void compute_planes(uint32_t sb, int wm, int wn, int lrow,
                                               int lhalf, float (&acc)[4][4][4]) {
#pragma unroll 1
    for (int kc = 0; kc < 8; kc++) {
        int k0 = kc * 16;
        unsigned Ah[4][4], Al[4][4], Bh[2][4], Bl[2][4];
#pragma unroll
        for (int mf = 0; mf < 4; mf++) {
            uint32_t a = sb + ((wm + mf * 16 + lrow) * PITCH + k0 + lhalf) * 2;
            ldsm_x4(Ah[mf], a + AH_OFF);
            ldsm_x4(Al[mf], a + AL_OFF);
        }
#pragma unroll
        for (int np = 0; np < 2; np++) {
            uint32_t a = sb + ((k0 + lrow) * PITCH + wn + np * 16 + lhalf) * 2;
            ldsm_x4_t(Bh[np], a + BH_OFF);
            ldsm_x4_t(Bl[np], a + BL_OFF);
        }
#pragma unroll
        for (int mf = 0; mf < 4; mf++)
#pragma unroll
            for (int nf = 0; nf < 4; nf++) {
                const unsigned* bh = &Bh[nf >> 1][(nf & 1) * 2];
                const unsigned* bl = &Bl[nf >> 1][(nf & 1) * 2];
                mma_bf16(acc[mf][nf], Ah[mf], bh);
                mma_bf16(acc[mf][nf], Al[mf], bh);
                mma_bf16(acc[mf][nf], Ah[mf], bl);
            }
    }
}

// y1 kernel: A = h0 (fp32), 2 relations per block (A planes loaded once)
__global__ void __launch_bounds__(256)
y1_k(const float* __restrict__ A, int M, const float* __restrict__ w1) {
    extern __shared__ char sm[];
    const uint32_t sb = smem_u32(sm);
    const int tid = threadIdx.x;
    const int lane = tid & 31;
    const int warp = tid >> 5;
    const int wm = (warp >> 2) * 64;
    const int wn = (warp & 3) * 32;
    const int m0 = blockIdx.x * 128;
    const int lrow = lane & 15;
    const int lhalf = (lane >> 4) * 8;

    load_A_f32(sm, A, HDIM, m0, M, tid);

#pragma unroll 1
    for (int rr = 0; rr < 2; rr++) {
        int r = blockIdx.z * 2 + rr;
        load_B_f32(sm, w1 + (size_t)r * HDIM * HDIM, tid);
        __syncthreads();

        float acc[4][4][4];
#pragma unroll
        for (int i = 0; i < 4; i++)
#pragma unroll
            for (int j = 0; j < 4; j++)
#pragma unroll
                for (int k = 0; k < 4; k++) acc[i][j][k] = 0.f;

        compute_planes(sb, wm, wn, lrow, lhalf, acc);

#pragma unroll
        for (int mf = 0; mf < 4; mf++)
#pragma unroll
            for (int nf = 0; nf < 4; nf++) {
                int r0 = m0 + wm + mf * 16 + (lane >> 2);
                int r1 = r0 + 8;
                int cl = wn + nf * 8 + (lane & 3) * 2;
                if (r0 < M)
                    *(__half2*)(g_y1h + (size_t)r0 * (RREL * HDIM) + r * HDIM + cl) =
                        __floats2half2_rn(acc[mf][nf][0], acc[mf][nf][1]);
                if (r1 < M)
                    *(__half2*)(g_y1h + (size_t)r1 * (RREL * HDIM) + r * HDIM + cl) =
                        __floats2half2_rn(acc[mf][nf][2], acc[mf][nf][3]);
            }
        __syncthreads();   // protect B planes before next relation's load
    }
}

// root1 kernel: h1h[repo] = relu(h0 @ root1 + b1) -> fp16
__global__ void __launch_bounds__(256)
root1_k(const float* __restrict__ A, int M, const float* __restrict__ B,
        const float* __restrict__ bias) {
    extern __shared__ char sm[];
    const uint32_t sb = smem_u32(sm);
    const int tid = threadIdx.x;
    const int lane = tid & 31;
    const int warp = tid >> 5;
    const int wm = (warp >> 2) * 64;
    const int wn = (warp & 3) * 32;
    const int m0 = blockIdx.x * 128;
    const int lrow = lane & 15;
    const int lhalf = (lane >> 4) * 8;

    load_A_f32(sm, A, HDIM, m0, M, tid);
    load_B_f32(sm, B, tid);
    __syncthreads();

    float acc[4][4][4];
#pragma unroll
    for (int i = 0; i < 4; i++)
#pragma unroll
        for (int j = 0; j < 4; j++)
#pragma unroll
            for (int k = 0; k < 4; k++) acc[i][j][k] = 0.f;

    compute_planes(sb, wm, wn, lrow, lhalf, acc);

#pragma unroll
    for (int mf = 0; mf < 4; mf++)
#pragma unroll
        for (int nf = 0; nf < 4; nf++) {
            int r0 = m0 + wm + mf * 16 + (lane >> 2);
            int r1 = r0 + 8;
            int cl = wn + nf * 8 + (lane & 3) * 2;
            float b0 = bias[cl], b1v = bias[cl + 1];
            if (r0 < M)
                *(__half2*)(g_h1h + (size_t)r0 * HDIM + cl) =
                    __floats2half2_rn(fmaxf(acc[mf][nf][0] + b0, 0.f),
                                      fmaxf(acc[mf][nf][1] + b1v, 0.f));
            if (r1 < M)
                *(__half2*)(g_h1h + (size_t)r1 * HDIM + cl) =
                    __floats2half2_rn(fmaxf(acc[mf][nf][2] + b0, 0.f),
                                      fmaxf(acc[mf][nf][3] + b1v, 0.f));
        }
}

// fused layer-2: acc = sum2h @ w2 (8 slabs) + h1h @ root2, then relu(+b2),
// classifier, write out[M,2]. A-side fp16 (exact split).
__global__ void __launch_bounds__(256)
l2_k(const __half* __restrict__ sum2, const __half* __restrict__ h1,
     const float* __restrict__ w2, const float* __restrict__ root2,
     const float* __restrict__ b2, const float* __restrict__ clsw,
     const float* __restrict__ clsb, float* __restrict__ out, int M) {
    extern __shared__ char sm[];
    const uint32_t sb = smem_u32(sm);
    const int tid = threadIdx.x;
    const int lane = tid & 31;
    const int warp = tid >> 5;
    const int wm = (warp >> 2) * 64;
    const int wn = (warp & 3) * 32;
    const int m0 = blockIdx.x * 128;
    const int lrow = lane & 15;
    const int lhalf = (lane >> 4) * 8;

    float acc[4][4][4];
#pragma unroll
    for (int i = 0; i < 4; i++)
#pragma unroll
        for (int j = 0; j < 4; j++)
#pragma unroll
            for (int k = 0; k < 4; k++) acc[i][j][k] = 0.f;

#pragma unroll 1
    for (int s = 0; s < 9; s++) {
        if (s < 8) load_A_f16(sm, sum2, RREL * HDIM, s * HDIM, m0, M, tid);
        else       load_A_f16(sm, h1, HDIM, 0, m0, M, tid);
        load_B_f32(sm, (s < 8) ? (w2 + (size_t)s * HDIM * HDIM) : root2, tid);
        __syncthreads();
        compute_planes(sb, wm, wn, lrow, lhalf, acc);
        __syncthreads();
    }

    float* redA = (float*)sm;
    float* redB = (float*)sm + 512;
#pragma unroll
    for (int mf = 0; mf < 4; mf++) {
        float p0a = 0.f, p0b = 0.f, p1a = 0.f, p1b = 0.f;
#pragma unroll
        for (int nf = 0; nf < 4; nf++) {
            int cl = wn + nf * 8 + (lane & 3) * 2;
            float b0 = b2[cl], b1v = b2[cl + 1];
            float w00 = clsw[cl * 2], w01 = clsw[cl * 2 + 1];
            float w10 = clsw[(cl + 1) * 2], w11 = clsw[(cl + 1) * 2 + 1];
            float v0 = fmaxf(acc[mf][nf][0] + b0, 0.f);
            float v1 = fmaxf(acc[mf][nf][1] + b1v, 0.f);
            float v2 = fmaxf(acc[mf][nf][2] + b0, 0.f);
            float v3 = fmaxf(acc[mf][nf][3] + b1v, 0.f);
            p0a += v0 * w00 + v1 * w10; p0b += v0 * w01 + v1 * w11;
            p1a += v2 * w00 + v3 * w10; p1b += v2 * w01 + v3 * w11;
        }
#pragma unroll
        for (int o = 1; o <= 2; o <<= 1) {
            p0a += __shfl_xor_sync(0xffffffffu, p0a, o);
            p0b += __shfl_xor_sync(0xffffffffu, p0b, o);
            p1a += __shfl_xor_sync(0xffffffffu, p1a, o);
            p1b += __shfl_xor_sync(0xffffffffu, p1b, o);
        }
        if ((lane & 3) == 0) {
            int r0 = wm + mf * 16 + (lane >> 2);
            redA[r0 * 4 + (warp & 3)] = p0a;
            redB[r0 * 4 + (warp & 3)] = p0b;
            redA[(r0 + 8) * 4 + (warp & 3)] = p1a;
            redB[(r0 + 8) * 4 + (warp & 3)] = p1b;
        }
    }
    __syncthreads();
    if (tid < 128) {
        int gr = m0 + tid;
        if (gr < M) {
            float o0 = redA[tid * 4] + redA[tid * 4 + 1] + redA[tid * 4 + 2] + redA[tid * 4 + 3] + clsb[0];
            float o1 = redB[tid * 4] + redB[tid * 4 + 1] + redB[tid * 4 + 2] + redB[tid * 4 + 3] + clsb[1];
            out[gr * 2 + 0] = o0;
            out[gr * 2 + 1] = o1;
        }
    }
}

// ---------------- driver -----------------------------------------------------
extern "C" void kernel_launch(void* const* d_in, const int* in_sizes, int n_in,
                              void* d_out, int out_size) {
    const float* x     = (const float*)d_in[0];
    const int*   er    = (const int*)d_in[1];
    const int*   ea    = (const int*)d_in[2];
    const int*   et    = (const int*)d_in[3];
    const float* mlp_w = (const float*)d_in[4];
    const float* mlp_b = (const float*)d_in[5];
    const float* w1    = (const float*)d_in[6];
    const float* root1 = (const float*)d_in[7];
    const float* b1    = (const float*)d_in[8];
    const float* w2    = (const float*)d_in[9];
    const float* root2 = (const float*)d_in[10];
    const float* b2    = (const float*)d_in[11];
    const float* cls_w = (const float*)d_in[12];
    const float* cls_b = (const float*)d_in[13];
    int E = in_sizes[1];
    float* out = (float*)d_out;

    void *pH0, *pH1h, *pS2h, *pOff1, *pOff2, *pBs1, *pBs2, *pCnt1, *pCnt2, *pCur1, *pCur2;
    cudaGetSymbolAddress(&pH0, g_h0);
    cudaGetSymbolAddress(&pH1h, g_h1h);
    cudaGetSymbolAddress(&pS2h, g_sum2h);
    cudaGetSymbolAddress(&pCnt1, g_cnt1);
    cudaGetSymbolAddress(&pCnt2, g_cnt2);
    cudaGetSymbolAddress(&pOff1, g_off1);
    cudaGetSymbolAddress(&pOff2, g_off2);
    cudaGetSymbolAddress(&pCur1, g_cur1);
    cudaGetSymbolAddress(&pCur2, g_cur2);
    cudaGetSymbolAddress(&pBs1, g_bsum1);
    cudaGetSymbolAddress(&pBs2, g_bsum2);

    cudaFuncSetAttribute(y1_k, cudaFuncAttributeMaxDynamicSharedMemorySize, MMA_SMEM);
    cudaFuncSetAttribute(root1_k, cudaFuncAttributeMaxDynamicSharedMemorySize, MMA_SMEM);
    cudaFuncSetAttribute(l2_k, cudaFuncAttributeMaxDynamicSharedMemorySize, MMA_SMEM);

    // --- CSR construction ---
    zero_cnt_k<<<(B1 + 255) / 256, 256>>>();
    count_k<<<(E + 255) / 256, 256>>>(er, ea, et, E);
    scan_blk_k<<<NB1, 1024>>>((const int*)pCnt1, B1, (int*)pOff1, (int*)pBs1);
    scan_blk_k<<<NB2, 1024>>>((const int*)pCnt2, B2, (int*)pOff2, (int*)pBs2);
    scan_top_k<<<1, 1024>>>((int*)pBs1, NB1);
    scan_top_k<<<1, 1024>>>((int*)pBs2, NB2);
    scan_add_k<<<(B1 + 255) / 256, 256>>>((int*)pOff1, (const int*)pBs1, (int*)pCur1, B1);
    scan_add_k<<<(B2 + 255) / 256, 256>>>((int*)pOff2, (const int*)pBs2, (int*)pCur2, B2);
    place_k<<<(E + 255) / 256, 256>>>(er, ea, et, E);

    // --- dense front ---
    mlp_k<<<(NREPO * HDIM + 255) / 256, 256>>>(x, mlp_w, mlp_b);
    uroot_k<<<1, HDIM>>>(mlp_b, root1);

    const int GB = (NREPO + 127) / 128;   // 235
    // y1[repo,r] = h0 @ W1[r] -> fp16 (2 relations per block)
    y1_k<<<dim3(GB, 1, RREL / 2), 256, MMA_SMEM>>>((const float*)pH0, NREPO, w1);
    // h1h[repo] = relu(h0 @ root1 + b1) -> fp16
    root1_k<<<dim3(GB, 1, 1), 256, MMA_SMEM>>>((const float*)pH0, NREPO, root1, b1);

    // layer-1 aggregation (actor rows of h1h)
    agg1_k<<<(NUSER * 32 + 255) / 256, 256>>>(b1, E);

    // layer-2 aggregation -> fp16 means
    agg2_k<<<((size_t)B2 * 32 + 255) / 256, 256>>>();

    // fused layer-2 dense + classifier
    l2_k<<<GB, 256, MMA_SMEM>>>(
        (const __half*)pS2h, (const __half*)pH1h, w2, root2, b2, cls_w, cls_b, out, NREPO);
}

// round 9
// speedup vs baseline: 2.0923x; 1.0657x over previous
#include <cuda_runtime.h>
#include <cuda_bf16.h>
#include <cuda_fp16.h>
#include <cstdint>

#define NREPO 30000
#define NUSER 70000
#define NNODE 100000
#define RREL  8
#define HDIM  128
#define B1 (NUSER * RREL)
#define B2 (NREPO * RREL)
#define NB1 ((B1 + 1023) / 1024)
#define NB2 ((B2 + 1023) / 1024)
#define EMAX 1000000

// ---------------- scratch ----------------------------------------------------
__device__ float  g_h0[(size_t)NREPO * HDIM];
__device__ __half g_h1h[(size_t)NNODE * HDIM];
__device__ __half g_y1h[(size_t)B2 * HDIM];
__device__ __half g_sum2h[(size_t)B2 * HDIM];
__device__ float  g_uroot[HDIM];
__device__ int    g_cnt1[B1], g_off1[B1], g_cur1[B1], g_bsum1[NB1];
__device__ int    g_cnt2[B2], g_off2[B2], g_cur2[B2], g_bsum2[NB2];
__device__ int    g_perm1[EMAX];
__device__ int    g_perm2[EMAX];

// ---------------- counting / CSR build ---------------------------------------
__global__ void zero_cnt_k() {
    int i = blockIdx.x * blockDim.x + threadIdx.x;
    if (i < B1) g_cnt1[i] = 0;
    if (i < B2) g_cnt2[i] = 0;
}

__global__ void count_k(const int* __restrict__ er, const int* __restrict__ ea,
                        const int* __restrict__ et, int E) {
    int e = blockIdx.x * blockDim.x + threadIdx.x;
    if (e >= E) return;
    atomicAdd(&g_cnt1[ea[e] * RREL + et[e]], 1);
    atomicAdd(&g_cnt2[er[e] * RREL + et[e]], 1);
}

// both arrays in one launch: blocks [0,NB1) -> layer1, [NB1,NB1+NB2) -> layer2
__global__ void scan_blk_all_k() {
    __shared__ int s[1024];
    int t = threadIdx.x;
    bool first = blockIdx.x < NB1;
    int blk = first ? blockIdx.x : blockIdx.x - NB1;
    const int* cnt = first ? g_cnt1 : g_cnt2;
    int* off = first ? g_off1 : g_off2;
    int* bsum = first ? g_bsum1 : g_bsum2;
    int n = first ? B1 : B2;
    int i = blk * 1024 + t;
    int v = (i < n) ? cnt[i] : 0;
    s[t] = v;
    __syncthreads();
#pragma unroll
    for (int d = 1; d < 1024; d <<= 1) {
        int u = (t >= d) ? s[t - d] : 0;
        __syncthreads();
        s[t] += u;
        __syncthreads();
    }
    if (i < n) off[i] = s[t] - v;
    if (t == 1023) bsum[blk] = s[1023];
}

// block 0 -> bsum1 (NB1), block 1 -> bsum2 (NB2)
__global__ void scan_top_all_k() {
    __shared__ int s[1024];
    int t = threadIdx.x;
    int* bsum = (blockIdx.x == 0) ? g_bsum1 : g_bsum2;
    int n = (blockIdx.x == 0) ? NB1 : NB2;
    int v = (t < n) ? bsum[t] : 0;
    s[t] = v;
    __syncthreads();
#pragma unroll
    for (int d = 1; d < 1024; d <<= 1) {
        int u = (t >= d) ? s[t - d] : 0;
        __syncthreads();
        s[t] += u;
        __syncthreads();
    }
    if (t < n) bsum[t] = s[t] - v;
}

__global__ void scan_add_all_k() {
    int i = blockIdx.x * blockDim.x + threadIdx.x;
    if (i < B1) {
        int o = g_off1[i] + g_bsum1[i >> 10];
        g_off1[i] = o;
        g_cur1[i] = o;
    } else if (i < B1 + B2) {
        int j = i - B1;
        int o = g_off2[j] + g_bsum2[j >> 10];
        g_off2[j] = o;
        g_cur2[j] = o;
    }
}

__global__ void place_k(const int* __restrict__ er, const int* __restrict__ ea,
                        const int* __restrict__ et, int E) {
    int e = blockIdx.x * blockDim.x + threadIdx.x;
    if (e >= E) return;
    int repo = er[e], actor = ea[e], t = et[e];
    int p1 = atomicAdd(&g_cur1[actor * RREL + t], 1);
    g_perm1[p1] = repo * RREL + t;
    int p2 = atomicAdd(&g_cur2[repo * RREL + t], 1);
    g_perm2[p2] = actor;
}

// ---------------- dense small pieces -----------------------------------------
__global__ void mlp_k(const float* __restrict__ x, const float* __restrict__ w,
                      const float* __restrict__ b) {
    int g = blockIdx.x * blockDim.x + threadIdx.x;
    if (g >= NREPO * HDIM) return;
    int n = g >> 7, o = g & 127;
    float acc = b[o];
#pragma unroll
    for (int k = 0; k < 8; k++) acc = fmaf(__ldg(&x[n * 8 + k]), __ldg(&w[k * HDIM + o]), acc);
    g_h0[g] = fmaxf(acc, 0.f);
}

// one block per output column, 128 threads reduce over k
__global__ void uroot_k(const float* __restrict__ mlp_b, const float* __restrict__ root1) {
    int o = blockIdx.x;
    int k = threadIdx.x;
    float v = fmaxf(mlp_b[k], 0.f) * root1[k * HDIM + o];
#pragma unroll
    for (int d = 16; d; d >>= 1) v += __shfl_xor_sync(0xffffffffu, v, d);
    __shared__ float s[4];
    if ((k & 31) == 0) s[k >> 5] = v;
    __syncthreads();
    if (k == 0) g_uroot[o] = s[0] + s[1] + s[2] + s[3];
}

// layer-1 aggregation: warp per actor, flat loop, shuffle-based inv lookup
__global__ void agg1_k(const float* __restrict__ b1, int E) {
    int w = (blockIdx.x * blockDim.x + threadIdx.x) >> 5;
    int lane = threadIdx.x & 31;
    if (w >= NUSER) return;
    float invreg = 0.f;
    if (lane < RREL) {
        int d = g_cnt1[w * RREL + lane];
        invreg = d ? 1.0f / (float)d : 0.f;
    }
    int start = g_off1[w * RREL];
    int end = (w * RREL + RREL < B1) ? g_off1[w * RREL + RREL] : E;
    float4 acc = *(const float4*)(g_uroot + lane * 4);

    int j = start;
    for (; j + 4 <= end; j += 4) {
        int p0 = __ldg(g_perm1 + j),     p1 = __ldg(g_perm1 + j + 1);
        int p2 = __ldg(g_perm1 + j + 2), p3 = __ldg(g_perm1 + j + 3);
        uint2 u0 = *(const uint2*)(g_y1h + (((size_t)p0) << 7) + lane * 4);
        uint2 u1 = *(const uint2*)(g_y1h + (((size_t)p1) << 7) + lane * 4);
        uint2 u2 = *(const uint2*)(g_y1h + (((size_t)p2) << 7) + lane * 4);
        uint2 u3 = *(const uint2*)(g_y1h + (((size_t)p3) << 7) + lane * 4);
        float iv0 = __shfl_sync(0xffffffffu, invreg, p0 & 7);
        float iv1 = __shfl_sync(0xffffffffu, invreg, p1 & 7);
        float iv2 = __shfl_sync(0xffffffffu, invreg, p2 & 7);
        float iv3 = __shfl_sync(0xffffffffu, invreg, p3 & 7);
#define ACC1(u, iv) { \
        float2 lo = __half22float2(((const __half2*)&(u))[0]); \
        float2 hi = __half22float2(((const __half2*)&(u))[1]); \
        acc.x = fmaf(lo.x, (iv), acc.x); acc.y = fmaf(lo.y, (iv), acc.y); \
        acc.z = fmaf(hi.x, (iv), acc.z); acc.w = fmaf(hi.y, (iv), acc.w); }
        ACC1(u0, iv0) ACC1(u1, iv1) ACC1(u2, iv2) ACC1(u3, iv3)
    }
    for (; j < end; j++) {
        int p0 = __ldg(g_perm1 + j);
        uint2 u0 = *(const uint2*)(g_y1h + (((size_t)p0) << 7) + lane * 4);
        float iv0 = __shfl_sync(0xffffffffu, invreg, p0 & 7);
        ACC1(u0, iv0)
    }
#undef ACC1
    const float4 bb = *(const float4*)(b1 + lane * 4);
    __half2 o0 = __floats2half2_rn(fmaxf(acc.x + bb.x, 0.f), fmaxf(acc.y + bb.y, 0.f));
    __half2 o1 = __floats2half2_rn(fmaxf(acc.z + bb.z, 0.f), fmaxf(acc.w + bb.w, 0.f));
    uint2 pk;
    pk.x = *(unsigned*)&o0; pk.y = *(unsigned*)&o1;
    *(uint2*)(g_h1h + (((size_t)(NREPO + w)) << 7) + lane * 4) = pk;
}

// layer-2 aggregation: warp per (repo, relation) bin
__global__ void agg2_k() {
    int bin = (blockIdx.x * blockDim.x + threadIdx.x) >> 5;
    int lane = threadIdx.x & 31;
    if (bin >= B2) return;
    int deg = g_cnt2[bin];
    int start = g_off2[bin];
    float4 s = make_float4(0.f, 0.f, 0.f, 0.f);
#define ACC2(u) { \
        float2 lo = __half22float2(((const __half2*)&(u))[0]); \
        float2 hi = __half22float2(((const __half2*)&(u))[1]); \
        s.x += lo.x; s.y += lo.y; s.z += hi.x; s.w += hi.y; }
    int j = 0;
    for (; j + 2 <= deg; j += 2) {
        int a0 = __ldg(g_perm2 + start + j);
        int a1 = __ldg(g_perm2 + start + j + 1);
        uint2 u0 = *(const uint2*)(g_h1h + (((size_t)(NREPO + a0)) << 7) + lane * 4);
        uint2 u1 = *(const uint2*)(g_h1h + (((size_t)(NREPO + a1)) << 7) + lane * 4);
        ACC2(u0) ACC2(u1)
    }
    if (j < deg) {
        int a0 = __ldg(g_perm2 + start + j);
        uint2 u0 = *(const uint2*)(g_h1h + (((size_t)(NREPO + a0)) << 7) + lane * 4);
        ACC2(u0)
    }
#undef ACC2
    float inv = deg ? 1.0f / (float)deg : 0.f;
    __half2 o0 = __floats2half2_rn(s.x * inv, s.y * inv);
    __half2 o1 = __floats2half2_rn(s.z * inv, s.w * inv);
    uint2 pk;
    pk.x = *(unsigned*)&o0; pk.y = *(unsigned*)&o1;
    *(uint2*)(g_sum2h + ((size_t)bin << 7) + lane * 4) = pk;
}

// ================= bf16 3-term tensor-core GEMM pieces =======================
#define PITCH 136
#define AH_OFF 0
#define AL_OFF 34816
#define BH_OFF 69632
#define BL_OFF 104448
#define MMA_SMEM 139264

__device__ __forceinline__ uint32_t smem_u32(const void* p) {
    uint32_t a;
    asm("{ .reg .u64 t; cvta.to.shared.u64 t, %1; cvt.u32.u64 %0, t; }" : "=r"(a) : "l"(p));
    return a;
}

__device__ __forceinline__ void ldsm_x4(unsigned r[4], uint32_t addr) {
    asm volatile("ldmatrix.sync.aligned.m8n8.x4.shared.b16 {%0,%1,%2,%3}, [%4];"
                 : "=r"(r[0]), "=r"(r[1]), "=r"(r[2]), "=r"(r[3]) : "r"(addr));
}

__device__ __forceinline__ void ldsm_x4_t(unsigned r[4], uint32_t addr) {
    asm volatile("ldmatrix.sync.aligned.m8n8.x4.trans.shared.b16 {%0,%1,%2,%3}, [%4];"
                 : "=r"(r[0]), "=r"(r[1]), "=r"(r[2]), "=r"(r[3]) : "r"(addr));
}

__device__ __forceinline__ void mma_bf16(float c[4], const unsigned a[4], const unsigned* b) {
    asm volatile(
        "mma.sync.aligned.m16n8k16.row.col.f32.bf16.bf16.f32 "
        "{%0,%1,%2,%3}, {%4,%5,%6,%7}, {%8,%9}, {%0,%1,%2,%3};"
        : "+f"(c[0]), "+f"(c[1]), "+f"(c[2]), "+f"(c[3])
        : "r"(a[0]), "r"(a[1]), "r"(a[2]), "r"(a[3]), "r"(b[0]), "r"(b[1]));
}

__device__ __forceinline__ void sp_bf(float x, unsigned short& h, unsigned short& l) {
    __nv_bfloat16 hb = __float2bfloat16_rn(x);
    h = __bfloat16_as_ushort(hb);
    l = __bfloat16_as_ushort(__float2bfloat16_rn(x - __bfloat162float(hb)));
}

__device__ __forceinline__ void store_planes(char* sm, int plane_off_h, int plane_off_l,
                                             int row, int c4, float4 f) {
    unsigned short h0, h1, h2, h3, l0, l1, l2, l3;
    sp_bf(f.x, h0, l0); sp_bf(f.y, h1, l1); sp_bf(f.z, h2, l2); sp_bf(f.w, h3, l3);
    int off = (row * PITCH + c4) * 2;
    *(uint2*)(sm + plane_off_h + off) = make_uint2((unsigned)h0 | ((unsigned)h1 << 16),
                                                   (unsigned)h2 | ((unsigned)h3 << 16));
    *(uint2*)(sm + plane_off_l + off) = make_uint2((unsigned)l0 | ((unsigned)l1 << 16),
                                                   (unsigned)l2 | ((unsigned)l3 << 16));
}

__device__ __forceinline__ void load_A_f32(char* sm, const float* __restrict__ A, int lda,
                                           int m0, int M, int tid) {
#pragma unroll
    for (int it = 0; it < 16; it++) {
        int v = tid + it * 256;
        int row = v >> 5;
        int c4 = (v & 31) * 4;
        float4 fa = (m0 + row < M) ? *(const float4*)(A + (size_t)(m0 + row) * lda + c4)
                                   : make_float4(0.f, 0.f, 0.f, 0.f);
        store_planes(sm, AH_OFF, AL_OFF, row, c4, fa);
    }
}

__device__ __forceinline__ void load_A_f16(char* sm, const __half* __restrict__ A, int lda,
                                           int cO, int m0, int M, int tid) {
#pragma unroll
    for (int it = 0; it < 16; it++) {
        int v = tid + it * 256;
        int row = v >> 5;
        int c4 = (v & 31) * 4;
        float4 fa = make_float4(0.f, 0.f, 0.f, 0.f);
        if (m0 + row < M) {
            uint2 u = *(const uint2*)(A + (size_t)(m0 + row) * lda + cO + c4);
            float2 lo = __half22float2(((const __half2*)&u)[0]);
            float2 hi = __half22float2(((const __half2*)&u)[1]);
            fa = make_float4(lo.x, lo.y, hi.x, hi.y);
        }
        store_planes(sm, AH_OFF, AL_OFF, row, c4, fa);
    }
}

__device__ __forceinline__ void load_B_f32(char* sm, const float* __restrict__ B, int tid) {
#pragma unroll
    for (int it = 0; it < 16; it++) {
        int v = tid + it * 256;
        int row = v >> 5;
        int c4 = (v & 31) * 4;
        float4 fb = *(const float4*)(B + (size_t)row * 128 + c4);
        store_planes(sm, BH_OFF, BL_OFF, row, c4, fb);
    }
}

__device__ __forceinline__ void compute_planes(uint32_t sb, int wm, int wn, int lrow,
                                               int lhalf, float (&acc)[4][4][4]) {
#pragma unroll 1
    for (int kc = 0; kc < 8; kc++) {
        int k0 = kc * 16;
        unsigned Ah[4][4], Al[4][4], Bh[2][4], Bl[2][4];
#pragma unroll
        for (int mf = 0; mf < 4; mf++) {
            uint32_t a = sb + ((wm + mf * 16 + lrow) * PITCH + k0 + lhalf) * 2;
            ldsm_x4(Ah[mf], a + AH_OFF);
            ldsm_x4(Al[mf], a + AL_OFF);
        }
#pragma unroll
        for (int np = 0; np < 2; np++) {
            uint32_t a = sb + ((k0 + lrow) * PITCH + wn + np * 16 + lhalf) * 2;
            ldsm_x4_t(Bh[np], a + BH_OFF);
            ldsm_x4_t(Bl[np], a + BL_OFF);
        }
#pragma unroll
        for (int mf = 0; mf < 4; mf++)
#pragma unroll
            for (int nf = 0; nf < 4; nf++) {
                const unsigned* bh = &Bh[nf >> 1][(nf & 1) * 2];
                const unsigned* bl = &Bl[nf >> 1][(nf & 1) * 2];
                mma_bf16(acc[mf][nf], Ah[mf], bh);
                mma_bf16(acc[mf][nf], Al[mf], bh);
                mma_bf16(acc[mf][nf], Ah[mf], bl);
            }
    }
}

// y1 kernel: A = h0 (fp32), 2 relations per block
__global__ void __launch_bounds__(256)
y1_k(const float* __restrict__ A, int M, const float* __restrict__ w1) {
    extern __shared__ char sm[];
    const uint32_t sb = smem_u32(sm);
    const int tid = threadIdx.x;
    const int lane = tid & 31;
    const int warp = tid >> 5;
    const int wm = (warp >> 2) * 64;
    const int wn = (warp & 3) * 32;
    const int m0 = blockIdx.x * 128;
    const int lrow = lane & 15;
    const int lhalf = (lane >> 4) * 8;

    load_A_f32(sm, A, HDIM, m0, M, tid);

#pragma unroll 1
    for (int rr = 0; rr < 2; rr++) {
        int r = blockIdx.z * 2 + rr;
        load_B_f32(sm, w1 + (size_t)r * HDIM * HDIM, tid);
        __syncthreads();

        float acc[4][4][4];
#pragma unroll
        for (int i = 0; i < 4; i++)
#pragma unroll
            for (int j = 0; j < 4; j++)
#pragma unroll
                for (int k = 0; k < 4; k++) acc[i][j][k] = 0.f;

        compute_planes(sb, wm, wn, lrow, lhalf, acc);

#pragma unroll
        for (int mf = 0; mf < 4; mf++)
#pragma unroll
            for (int nf = 0; nf < 4; nf++) {
                int r0 = m0 + wm + mf * 16 + (lane >> 2);
                int r1 = r0 + 8;
                int cl = wn + nf * 8 + (lane & 3) * 2;
                if (r0 < M)
                    *(__half2*)(g_y1h + (size_t)r0 * (RREL * HDIM) + r * HDIM + cl) =
                        __floats2half2_rn(acc[mf][nf][0], acc[mf][nf][1]);
                if (r1 < M)
                    *(__half2*)(g_y1h + (size_t)r1 * (RREL * HDIM) + r * HDIM + cl) =
                        __floats2half2_rn(acc[mf][nf][2], acc[mf][nf][3]);
            }
        __syncthreads();
    }
}

// root1 kernel: h1h[repo] = relu(h0 @ root1 + b1) -> fp16
__global__ void __launch_bounds__(256)
root1_k(const float* __restrict__ A, int M, const float* __restrict__ B,
        const float* __restrict__ bias) {
    extern __shared__ char sm[];
    const uint32_t sb = smem_u32(sm);
    const int tid = threadIdx.x;
    const int lane = tid & 31;
    const int warp = tid >> 5;
    const int wm = (warp >> 2) * 64;
    const int wn = (warp & 3) * 32;
    const int m0 = blockIdx.x * 128;
    const int lrow = lane & 15;
    const int lhalf = (lane >> 4) * 8;

    load_A_f32(sm, A, HDIM, m0, M, tid);
    load_B_f32(sm, B, tid);
    __syncthreads();

    float acc[4][4][4];
#pragma unroll
    for (int i = 0; i < 4; i++)
#pragma unroll
        for (int j = 0; j < 4; j++)
#pragma unroll
            for (int k = 0; k < 4; k++) acc[i][j][k] = 0.f;

    compute_planes(sb, wm, wn, lrow, lhalf, acc);

#pragma unroll
    for (int mf = 0; mf < 4; mf++)
#pragma unroll
        for (int nf = 0; nf < 4; nf++) {
            int r0 = m0 + wm + mf * 16 + (lane >> 2);
            int r1 = r0 + 8;
            int cl = wn + nf * 8 + (lane & 3) * 2;
            float b0 = bias[cl], b1v = bias[cl + 1];
            if (r0 < M)
                *(__half2*)(g_h1h + (size_t)r0 * HDIM + cl) =
                    __floats2half2_rn(fmaxf(acc[mf][nf][0] + b0, 0.f),
                                      fmaxf(acc[mf][nf][1] + b1v, 0.f));
            if (r1 < M)
                *(__half2*)(g_h1h + (size_t)r1 * HDIM + cl) =
                    __floats2half2_rn(fmaxf(acc[mf][nf][2] + b0, 0.f),
                                      fmaxf(acc[mf][nf][3] + b1v, 0.f));
        }
}

// fused layer-2 + classifier
__global__ void __launch_bounds__(256)
l2_k(const __half* __restrict__ sum2, const __half* __restrict__ h1,
     const float* __restrict__ w2, const float* __restrict__ root2,
     const float* __restrict__ b2, const float* __restrict__ clsw,
     const float* __restrict__ clsb, float* __restrict__ out, int M) {
    extern __shared__ char sm[];
    const uint32_t sb = smem_u32(sm);
    const int tid = threadIdx.x;
    const int lane = tid & 31;
    const int warp = tid >> 5;
    const int wm = (warp >> 2) * 64;
    const int wn = (warp & 3) * 32;
    const int m0 = blockIdx.x * 128;
    const int lrow = lane & 15;
    const int lhalf = (lane >> 4) * 8;

    float acc[4][4][4];
#pragma unroll
    for (int i = 0; i < 4; i++)
#pragma unroll
        for (int j = 0; j < 4; j++)
#pragma unroll
            for (int k = 0; k < 4; k++) acc[i][j][k] = 0.f;

#pragma unroll 1
    for (int s = 0; s < 9; s++) {
        if (s < 8) load_A_f16(sm, sum2, RREL * HDIM, s * HDIM, m0, M, tid);
        else       load_A_f16(sm, h1, HDIM, 0, m0, M, tid);
        load_B_f32(sm, (s < 8) ? (w2 + (size_t)s * HDIM * HDIM) : root2, tid);
        __syncthreads();
        compute_planes(sb, wm, wn, lrow, lhalf, acc);
        __syncthreads();
    }

    float* redA = (float*)sm;
    float* redB = (float*)sm + 512;
#pragma unroll
    for (int mf = 0; mf < 4; mf++) {
        float p0a = 0.f, p0b = 0.f, p1a = 0.f, p1b = 0.f;
#pragma unroll
        for (int nf = 0; nf < 4; nf++) {
            int cl = wn + nf * 8 + (lane & 3) * 2;
            float b0 = b2[cl], b1v = b2[cl + 1];
            float w00 = clsw[cl * 2], w01 = clsw[cl * 2 + 1];
            float w10 = clsw[(cl + 1) * 2], w11 = clsw[(cl + 1) * 2 + 1];
            float v0 = fmaxf(acc[mf][nf][0] + b0, 0.f);
            float v1 = fmaxf(acc[mf][nf][1] + b1v, 0.f);
            float v2 = fmaxf(acc[mf][nf][2] + b0, 0.f);
            float v3 = fmaxf(acc[mf][nf][3] + b1v, 0.f);
            p0a += v0 * w00 + v1 * w10; p0b += v0 * w01 + v1 * w11;
            p1a += v2 * w00 + v3 * w10; p1b += v2 * w01 + v3 * w11;
        }
#pragma unroll
        for (int o = 1; o <= 2; o <<= 1) {
            p0a += __shfl_xor_sync(0xffffffffu, p0a, o);
            p0b += __shfl_xor_sync(0xffffffffu, p0b, o);
            p1a += __shfl_xor_sync(0xffffffffu, p1a, o);
            p1b += __shfl_xor_sync(0xffffffffu, p1b, o);
        }
        if ((lane & 3) == 0) {
            int r0 = wm + mf * 16 + (lane >> 2);
            redA[r0 * 4 + (warp & 3)] = p0a;
            redB[r0 * 4 + (warp & 3)] = p0b;
            redA[(r0 + 8) * 4 + (warp & 3)] = p1a;
            redB[(r0 + 8) * 4 + (warp & 3)] = p1b;
        }
    }
    __syncthreads();
    if (tid < 128) {
        int gr = m0 + tid;
        if (gr < M) {
            float o0 = redA[tid * 4] + redA[tid * 4 + 1] + redA[tid * 4 + 2] + redA[tid * 4 + 3] + clsb[0];
            float o1 = redB[tid * 4] + redB[tid * 4 + 1] + redB[tid * 4 + 2] + redB[tid * 4 + 3] + clsb[1];
            out[gr * 2 + 0] = o0;
            out[gr * 2 + 1] = o1;
        }
    }
}

// ---------------- driver (single stream) -------------------------------------
extern "C" void kernel_launch(void* const* d_in, const int* in_sizes, int n_in,
                              void* d_out, int out_size) {
    const float* x     = (const float*)d_in[0];
    const int*   er    = (const int*)d_in[1];
    const int*   ea    = (const int*)d_in[2];
    const int*   et    = (const int*)d_in[3];
    const float* mlp_w = (const float*)d_in[4];
    const float* mlp_b = (const float*)d_in[5];
    const float* w1    = (const float*)d_in[6];
    const float* root1 = (const float*)d_in[7];
    const float* b1    = (const float*)d_in[8];
    const float* w2    = (const float*)d_in[9];
    const float* root2 = (const float*)d_in[10];
    const float* b2    = (const float*)d_in[11];
    const float* cls_w = (const float*)d_in[12];
    const float* cls_b = (const float*)d_in[13];
    int E = in_sizes[1];
    float* out = (float*)d_out;

    void *pH0, *pH1h, *pS2h;
    cudaGetSymbolAddress(&pH0, g_h0);
    cudaGetSymbolAddress(&pH1h, g_h1h);
    cudaGetSymbolAddress(&pS2h, g_sum2h);

    cudaFuncSetAttribute(y1_k, cudaFuncAttributeMaxDynamicSharedMemorySize, MMA_SMEM);
    cudaFuncSetAttribute(root1_k, cudaFuncAttributeMaxDynamicSharedMemorySize, MMA_SMEM);
    cudaFuncSetAttribute(l2_k, cudaFuncAttributeMaxDynamicSharedMemorySize, MMA_SMEM);

    const int GB = (NREPO + 127) / 128;   // 235

    // --- CSR construction ---
    zero_cnt_k<<<(B1 + 255) / 256, 256>>>();
    count_k<<<(E + 255) / 256, 256>>>(er, ea, et, E);
    scan_blk_all_k<<<NB1 + NB2, 1024>>>();
    scan_top_all_k<<<2, 1024>>>();
    scan_add_all_k<<<(B1 + B2 + 255) / 256, 256>>>();
    place_k<<<(E + 255) / 256, 256>>>(er, ea, et, E);

    // --- dense front ---
    mlp_k<<<(NREPO * HDIM + 255) / 256, 256>>>(x, mlp_w, mlp_b);
    uroot_k<<<HDIM, 128>>>(mlp_b, root1);
    y1_k<<<dim3(GB, 1, RREL / 2), 256, MMA_SMEM>>>((const float*)pH0, NREPO, w1);
    root1_k<<<dim3(GB, 1, 1), 256, MMA_SMEM>>>((const float*)pH0, NREPO, root1, b1);

    // layer-1 aggregation (actor rows of h1h)
    agg1_k<<<(NUSER * 32 + 255) / 256, 256>>>(b1, E);

    // layer-2 aggregation -> fp16 means
    agg2_k<<<((size_t)B2 * 32 + 255) / 256, 256>>>();

    // fused layer-2 dense + classifier
    l2_k<<<GB, 256, MMA_SMEM>>>(
        (const __half*)pS2h, (const __half*)pH1h, w2, root2, b2, cls_w, cls_b, out, NREPO);
}

// round 10
// speedup vs baseline: 2.1341x; 1.0200x over previous
#include <cuda_runtime.h>
#include <cuda_bf16.h>
#include <cuda_fp16.h>
#include <cstdint>

#define NREPO 30000
#define NUSER 70000
#define NNODE 100000
#define RREL  8
#define HDIM  128
#define B1 (NUSER * RREL)
#define B2 (NREPO * RREL)
#define NB1 ((B1 + 1023) / 1024)
#define NB2 ((B2 + 1023) / 1024)
#define EMAX 1000000

// fused front kernel block ranges
#define ZBLKS ((B1 + 255) / 256)                 // 2188: zero counters
#define MBLKS ((NREPO * HDIM + 255) / 256)       // 15000: mlp
#define UBLKS (HDIM / 2)                         // 64: uroot (2 cols/block)

// ---------------- scratch ----------------------------------------------------
__device__ float  g_h0[(size_t)NREPO * HDIM];
__device__ __half g_h1h[(size_t)NNODE * HDIM];
__device__ __half g_y1h[(size_t)B2 * HDIM];
__device__ __half g_sum2h[(size_t)B2 * HDIM];
__device__ float  g_uroot[HDIM];
__device__ int    g_cnt1[B1], g_off1[B1], g_cur1[B1], g_bsum1[NB1];
__device__ int    g_cnt2[B2], g_off2[B2], g_cur2[B2], g_bsum2[NB2];
__device__ int    g_perm1[EMAX];
__device__ int    g_perm2[EMAX];

// ---------------- fused front: zero counters | mlp | uroot -------------------
__global__ void front_k(const float* __restrict__ x, const float* __restrict__ mlp_w,
                        const float* __restrict__ mlp_b, const float* __restrict__ root1) {
    int bx = blockIdx.x;
    int tid = threadIdx.x;
    if (bx < ZBLKS) {
        int i = bx * 256 + tid;
        if (i < B1) g_cnt1[i] = 0;
        if (i < B2) g_cnt2[i] = 0;
        return;
    }
    bx -= ZBLKS;
    if (bx < MBLKS) {
        int g = bx * 256 + tid;
        if (g >= NREPO * HDIM) return;
        int n = g >> 7, o = g & 127;
        float acc = mlp_b[o];
#pragma unroll
        for (int k = 0; k < 8; k++)
            acc = fmaf(__ldg(&x[n * 8 + k]), __ldg(&mlp_w[k * HDIM + o]), acc);
        g_h0[g] = fmaxf(acc, 0.f);
        return;
    }
    bx -= MBLKS;
    // uroot: 2 output columns per block, 128 threads each
    {
        int half = tid >> 7;           // 0/1
        int k = tid & 127;
        int o = bx * 2 + half;
        float v = fmaxf(mlp_b[k], 0.f) * root1[k * HDIM + o];
#pragma unroll
        for (int d = 16; d; d >>= 1) v += __shfl_xor_sync(0xffffffffu, v, d);
        __shared__ float s[8];
        int w = tid >> 5;
        if ((tid & 31) == 0) s[w] = v;
        __syncthreads();
        if (k == 0) g_uroot[o] = s[half * 4] + s[half * 4 + 1] + s[half * 4 + 2] + s[half * 4 + 3];
    }
}

// ---------------- counting / CSR build ---------------------------------------
__global__ void count_k(const int* __restrict__ er, const int* __restrict__ ea,
                        const int* __restrict__ et, int E) {
    int e = blockIdx.x * blockDim.x + threadIdx.x;
    if (e >= E) return;
    atomicAdd(&g_cnt1[ea[e] * RREL + et[e]], 1);
    atomicAdd(&g_cnt2[er[e] * RREL + et[e]], 1);
}

__global__ void scan_blk_all_k() {
    __shared__ int s[1024];
    int t = threadIdx.x;
    bool first = blockIdx.x < NB1;
    int blk = first ? blockIdx.x : blockIdx.x - NB1;
    const int* cnt = first ? g_cnt1 : g_cnt2;
    int* off = first ? g_off1 : g_off2;
    int* bsum = first ? g_bsum1 : g_bsum2;
    int n = first ? B1 : B2;
    int i = blk * 1024 + t;
    int v = (i < n) ? cnt[i] : 0;
    s[t] = v;
    __syncthreads();
#pragma unroll
    for (int d = 1; d < 1024; d <<= 1) {
        int u = (t >= d) ? s[t - d] : 0;
        __syncthreads();
        s[t] += u;
        __syncthreads();
    }
    if (i < n) off[i] = s[t] - v;
    if (t == 1023) bsum[blk] = s[1023];
}

__global__ void scan_top_all_k() {
    __shared__ int s[1024];
    int t = threadIdx.x;
    int* bsum = (blockIdx.x == 0) ? g_bsum1 : g_bsum2;
    int n = (blockIdx.x == 0) ? NB1 : NB2;
    int v = (t < n) ? bsum[t] : 0;
    s[t] = v;
    __syncthreads();
#pragma unroll
    for (int d = 1; d < 1024; d <<= 1) {
        int u = (t >= d) ? s[t - d] : 0;
        __syncthreads();
        s[t] += u;
        __syncthreads();
    }
    if (t < n) bsum[t] = s[t] - v;
}

__global__ void scan_add_all_k() {
    int i = blockIdx.x * blockDim.x + threadIdx.x;
    if (i < B1) {
        int o = g_off1[i] + g_bsum1[i >> 10];
        g_off1[i] = o;
        g_cur1[i] = o;
    } else if (i < B1 + B2) {
        int j = i - B1;
        int o = g_off2[j] + g_bsum2[j >> 10];
        g_off2[j] = o;
        g_cur2[j] = o;
    }
}

__global__ void place_k(const int* __restrict__ er, const int* __restrict__ ea,
                        const int* __restrict__ et, int E) {
    int e = blockIdx.x * blockDim.x + threadIdx.x;
    if (e >= E) return;
    int repo = er[e], actor = ea[e], t = et[e];
    int p1 = atomicAdd(&g_cur1[actor * RREL + t], 1);
    g_perm1[p1] = repo * RREL + t;
    int p2 = atomicAdd(&g_cur2[repo * RREL + t], 1);
    g_perm2[p2] = actor;
}

// ---------------- aggregations ------------------------------------------------
// layer-1: warp per actor, flat edge loop, shuffle-based inv lookup
__global__ void agg1_k(const float* __restrict__ b1, int E) {
    int w = (blockIdx.x * blockDim.x + threadIdx.x) >> 5;
    int lane = threadIdx.x & 31;
    if (w >= NUSER) return;
    float invreg = 0.f;
    if (lane < RREL) {
        int d = g_cnt1[w * RREL + lane];
        invreg = d ? 1.0f / (float)d : 0.f;
    }
    int start = g_off1[w * RREL];
    int end = (w * RREL + RREL < B1) ? g_off1[w * RREL + RREL] : E;
    float4 acc = *(const float4*)(g_uroot + lane * 4);

    int j = start;
    for (; j + 4 <= end; j += 4) {
        int p0 = __ldg(g_perm1 + j),     p1 = __ldg(g_perm1 + j + 1);
        int p2 = __ldg(g_perm1 + j + 2), p3 = __ldg(g_perm1 + j + 3);
        uint2 u0 = *(const uint2*)(g_y1h + (((size_t)p0) << 7) + lane * 4);
        uint2 u1 = *(const uint2*)(g_y1h + (((size_t)p1) << 7) + lane * 4);
        uint2 u2 = *(const uint2*)(g_y1h + (((size_t)p2) << 7) + lane * 4);
        uint2 u3 = *(const uint2*)(g_y1h + (((size_t)p3) << 7) + lane * 4);
        float iv0 = __shfl_sync(0xffffffffu, invreg, p0 & 7);
        float iv1 = __shfl_sync(0xffffffffu, invreg, p1 & 7);
        float iv2 = __shfl_sync(0xffffffffu, invreg, p2 & 7);
        float iv3 = __shfl_sync(0xffffffffu, invreg, p3 & 7);
#define ACC1(u, iv) { \
        float2 lo = __half22float2(((const __half2*)&(u))[0]); \
        float2 hi = __half22float2(((const __half2*)&(u))[1]); \
        acc.x = fmaf(lo.x, (iv), acc.x); acc.y = fmaf(lo.y, (iv), acc.y); \
        acc.z = fmaf(hi.x, (iv), acc.z); acc.w = fmaf(hi.y, (iv), acc.w); }
        ACC1(u0, iv0) ACC1(u1, iv1) ACC1(u2, iv2) ACC1(u3, iv3)
    }
    for (; j < end; j++) {
        int p0 = __ldg(g_perm1 + j);
        uint2 u0 = *(const uint2*)(g_y1h + (((size_t)p0) << 7) + lane * 4);
        float iv0 = __shfl_sync(0xffffffffu, invreg, p0 & 7);
        ACC1(u0, iv0)
    }
#undef ACC1
    const float4 bb = *(const float4*)(b1 + lane * 4);
    __half2 o0 = __floats2half2_rn(fmaxf(acc.x + bb.x, 0.f), fmaxf(acc.y + bb.y, 0.f));
    __half2 o1 = __floats2half2_rn(fmaxf(acc.z + bb.z, 0.f), fmaxf(acc.w + bb.w, 0.f));
    uint2 pk;
    pk.x = *(unsigned*)&o0; pk.y = *(unsigned*)&o1;
    *(uint2*)(g_h1h + (((size_t)(NREPO + w)) << 7) + lane * 4) = pk;
}

// layer-2: warp per (repo, relation) bin, 4-way unrolled edge loop
__global__ void agg2_k() {
    int bin = (blockIdx.x * blockDim.x + threadIdx.x) >> 5;
    int lane = threadIdx.x & 31;
    if (bin >= B2) return;
    int deg = g_cnt2[bin];
    int start = g_off2[bin];
    float4 s = make_float4(0.f, 0.f, 0.f, 0.f);
#define ACC2(u) { \
        float2 lo = __half22float2(((const __half2*)&(u))[0]); \
        float2 hi = __half22float2(((const __half2*)&(u))[1]); \
        s.x += lo.x; s.y += lo.y; s.z += hi.x; s.w += hi.y; }
    int j = 0;
    for (; j + 4 <= deg; j += 4) {
        int a0 = __ldg(g_perm2 + start + j);
        int a1 = __ldg(g_perm2 + start + j + 1);
        int a2 = __ldg(g_perm2 + start + j + 2);
        int a3 = __ldg(g_perm2 + start + j + 3);
        uint2 u0 = *(const uint2*)(g_h1h + (((size_t)(NREPO + a0)) << 7) + lane * 4);
        uint2 u1 = *(const uint2*)(g_h1h + (((size_t)(NREPO + a1)) << 7) + lane * 4);
        uint2 u2 = *(const uint2*)(g_h1h + (((size_t)(NREPO + a2)) << 7) + lane * 4);
        uint2 u3 = *(const uint2*)(g_h1h + (((size_t)(NREPO + a3)) << 7) + lane * 4);
        ACC2(u0) ACC2(u1) ACC2(u2) ACC2(u3)
    }
    for (; j < deg; j++) {
        int a0 = __ldg(g_perm2 + start + j);
        uint2 u0 = *(const uint2*)(g_h1h + (((size_t)(NREPO + a0)) << 7) + lane * 4);
        ACC2(u0)
    }
#undef ACC2
    float inv = deg ? 1.0f / (float)deg : 0.f;
    __half2 o0 = __floats2half2_rn(s.x * inv, s.y * inv);
    __half2 o1 = __floats2half2_rn(s.z * inv, s.w * inv);
    uint2 pk;
    pk.x = *(unsigned*)&o0; pk.y = *(unsigned*)&o1;
    *(uint2*)(g_sum2h + ((size_t)bin << 7) + lane * 4) = pk;
}

// ================= bf16 3-term tensor-core GEMM pieces =======================
#define PITCH 136
#define AH_OFF 0
#define AL_OFF 34816
#define BH_OFF 69632
#define BL_OFF 104448
#define MMA_SMEM 139264

__device__ __forceinline__ uint32_t smem_u32(const void* p) {
    uint32_t a;
    asm("{ .reg .u64 t; cvta.to.shared.u64 t, %1; cvt.u32.u64 %0, t; }" : "=r"(a) : "l"(p));
    return a;
}

__device__ __forceinline__ void ldsm_x4(unsigned r[4], uint32_t addr) {
    asm volatile("ldmatrix.sync.aligned.m8n8.x4.shared.b16 {%0,%1,%2,%3}, [%4];"
                 : "=r"(r[0]), "=r"(r[1]), "=r"(r[2]), "=r"(r[3]) : "r"(addr));
}

__device__ __forceinline__ void ldsm_x4_t(unsigned r[4], uint32_t addr) {
    asm volatile("ldmatrix.sync.aligned.m8n8.x4.trans.shared.b16 {%0,%1,%2,%3}, [%4];"
                 : "=r"(r[0]), "=r"(r[1]), "=r"(r[2]), "=r"(r[3]) : "r"(addr));
}

__device__ __forceinline__ void mma_bf16(float c[4], const unsigned a[4], const unsigned* b) {
    asm volatile(
        "mma.sync.aligned.m16n8k16.row.col.f32.bf16.bf16.f32 "
        "{%0,%1,%2,%3}, {%4,%5,%6,%7}, {%8,%9}, {%0,%1,%2,%3};"
        : "+f"(c[0]), "+f"(c[1]), "+f"(c[2]), "+f"(c[3])
        : "r"(a[0]), "r"(a[1]), "r"(a[2]), "r"(a[3]), "r"(b[0]), "r"(b[1]));
}

__device__ __forceinline__ void sp_bf(float x, unsigned short& h, unsigned short& l) {
    __nv_bfloat16 hb = __float2bfloat16_rn(x);
    h = __bfloat16_as_ushort(hb);
    l = __bfloat16_as_ushort(__float2bfloat16_rn(x - __bfloat162float(hb)));
}

__device__ __forceinline__ void store_planes(char* sm, int plane_off_h, int plane_off_l,
                                             int row, int c4, float4 f) {
    unsigned short h0, h1, h2, h3, l0, l1, l2, l3;
    sp_bf(f.x, h0, l0); sp_bf(f.y, h1, l1); sp_bf(f.z, h2, l2); sp_bf(f.w, h3, l3);
    int off = (row * PITCH + c4) * 2;
    *(uint2*)(sm + plane_off_h + off) = make_uint2((unsigned)h0 | ((unsigned)h1 << 16),
                                                   (unsigned)h2 | ((unsigned)h3 << 16));
    *(uint2*)(sm + plane_off_l + off) = make_uint2((unsigned)l0 | ((unsigned)l1 << 16),
                                                   (unsigned)l2 | ((unsigned)l3 << 16));
}

__device__ __forceinline__ void load_A_f32(char* sm, const float* __restrict__ A, int lda,
                                           int m0, int M, int tid) {
#pragma unroll
    for (int it = 0; it < 16; it++) {
        int v = tid + it * 256;
        int row = v >> 5;
        int c4 = (v & 31) * 4;
        float4 fa = (m0 + row < M) ? *(const float4*)(A + (size_t)(m0 + row) * lda + c4)
                                   : make_float4(0.f, 0.f, 0.f, 0.f);
        store_planes(sm, AH_OFF, AL_OFF, row, c4, fa);
    }
}

__device__ __forceinline__ void load_A_f16(char* sm, const __half* __restrict__ A, int lda,
                                           int cO, int m0, int M, int tid) {
#pragma unroll
    for (int it = 0; it < 16; it++) {
        int v = tid + it * 256;
        int row = v >> 5;
        int c4 = (v & 31) * 4;
        float4 fa = make_float4(0.f, 0.f, 0.f, 0.f);
        if (m0 + row < M) {
            uint2 u = *(const uint2*)(A + (size_t)(m0 + row) * lda + cO + c4);
            float2 lo = __half22float2(((const __half2*)&u)[0]);
            float2 hi = __half22float2(((const __half2*)&u)[1]);
            fa = make_float4(lo.x, lo.y, hi.x, hi.y);
        }
        store_planes(sm, AH_OFF, AL_OFF, row, c4, fa);
    }
}

__device__ __forceinline__ void load_B_f32(char* sm, const float* __restrict__ B, int tid) {
#pragma unroll
    for (int it = 0; it < 16; it++) {
        int v = tid + it * 256;
        int row = v >> 5;
        int c4 = (v & 31) * 4;
        float4 fb = *(const float4*)(B + (size_t)row * 128 + c4);
        store_planes(sm, BH_OFF, BL_OFF, row, c4, fb);
    }
}

__device__ __forceinline__ void compute_planes(uint32_t sb, int wm, int wn, int lrow,
                                               int lhalf, float (&acc)[4][4][4]) {
#pragma unroll 1
    for (int kc = 0; kc < 8; kc++) {
        int k0 = kc * 16;
        unsigned Ah[4][4], Al[4][4], Bh[2][4], Bl[2][4];
#pragma unroll
        for (int mf = 0; mf < 4; mf++) {
            uint32_t a = sb + ((wm + mf * 16 + lrow) * PITCH + k0 + lhalf) * 2;
            ldsm_x4(Ah[mf], a + AH_OFF);
            ldsm_x4(Al[mf], a + AL_OFF);
        }
#pragma unroll
        for (int np = 0; np < 2; np++) {
            uint32_t a = sb + ((k0 + lrow) * PITCH + wn + np * 16 + lhalf) * 2;
            ldsm_x4_t(Bh[np], a + BH_OFF);
            ldsm_x4_t(Bl[np], a + BL_OFF);
        }
#pragma unroll
        for (int mf = 0; mf < 4; mf++)
#pragma unroll
            for (int nf = 0; nf < 4; nf++) {
                const unsigned* bh = &Bh[nf >> 1][(nf & 1) * 2];
                const unsigned* bl = &Bl[nf >> 1][(nf & 1) * 2];
                mma_bf16(acc[mf][nf], Ah[mf], bh);
                mma_bf16(acc[mf][nf], Al[mf], bh);
                mma_bf16(acc[mf][nf], Ah[mf], bl);
            }
    }
}

// y1 + root1 fused: A = h0 (fp32) loaded once per block.
// z in [0,4): relations 2z, 2z+1 -> y1h.   z == 4: root1 -> h1h (bias+relu).
__global__ void __launch_bounds__(256)
y1root_k(const float* __restrict__ A, int M, const float* __restrict__ w1,
         const float* __restrict__ root1, const float* __restrict__ bias) {
    extern __shared__ char sm[];
    const uint32_t sb = smem_u32(sm);
    const int tid = threadIdx.x;
    const int lane = tid & 31;
    const int warp = tid >> 5;
    const int wm = (warp >> 2) * 64;
    const int wn = (warp & 3) * 32;
    const int m0 = blockIdx.x * 128;
    const int lrow = lane & 15;
    const int lhalf = (lane >> 4) * 8;
    const int z = blockIdx.z;
    const int nmat = (z == 4) ? 1 : 2;

    load_A_f32(sm, A, HDIM, m0, M, tid);

#pragma unroll 1
    for (int rr = 0; rr < nmat; rr++) {
        const float* B = (z == 4) ? root1 : (w1 + (size_t)(z * 2 + rr) * HDIM * HDIM);
        load_B_f32(sm, B, tid);
        __syncthreads();

        float acc[4][4][4];
#pragma unroll
        for (int i = 0; i < 4; i++)
#pragma unroll
            for (int j = 0; j < 4; j++)
#pragma unroll
                for (int k = 0; k < 4; k++) acc[i][j][k] = 0.f;

        compute_planes(sb, wm, wn, lrow, lhalf, acc);

#pragma unroll
        for (int mf = 0; mf < 4; mf++)
#pragma unroll
            for (int nf = 0; nf < 4; nf++) {
                int r0 = m0 + wm + mf * 16 + (lane >> 2);
                int r1 = r0 + 8;
                int cl = wn + nf * 8 + (lane & 3) * 2;
                if (z == 4) {
                    float b0 = bias[cl], b1v = bias[cl + 1];
                    if (r0 < M)
                        *(__half2*)(g_h1h + (size_t)r0 * HDIM + cl) =
                            __floats2half2_rn(fmaxf(acc[mf][nf][0] + b0, 0.f),
                                              fmaxf(acc[mf][nf][1] + b1v, 0.f));
                    if (r1 < M)
                        *(__half2*)(g_h1h + (size_t)r1 * HDIM + cl) =
                            __floats2half2_rn(fmaxf(acc[mf][nf][2] + b0, 0.f),
                                              fmaxf(acc[mf][nf][3] + b1v, 0.f));
                } else {
                    int r = z * 2 + rr;
                    if (r0 < M)
                        *(__half2*)(g_y1h + (size_t)r0 * (RREL * HDIM) + r * HDIM + cl) =
                            __floats2half2_rn(acc[mf][nf][0], acc[mf][nf][1]);
                    if (r1 < M)
                        *(__half2*)(g_y1h + (size_t)r1 * (RREL * HDIM) + r * HDIM + cl) =
                            __floats2half2_rn(acc[mf][nf][2], acc[mf][nf][3]);
                }
            }
        __syncthreads();
    }
}

// fused layer-2 + classifier
__global__ void __launch_bounds__(256)
l2_k(const __half* __restrict__ sum2, const __half* __restrict__ h1,
     const float* __restrict__ w2, const float* __restrict__ root2,
     const float* __restrict__ b2, const float* __restrict__ clsw,
     const float* __restrict__ clsb, float* __restrict__ out, int M) {
    extern __shared__ char sm[];
    const uint32_t sb = smem_u32(sm);
    const int tid = threadIdx.x;
    const int lane = tid & 31;
    const int warp = tid >> 5;
    const int wm = (warp >> 2) * 64;
    const int wn = (warp & 3) * 32;
    const int m0 = blockIdx.x * 128;
    const int lrow = lane & 15;
    const int lhalf = (lane >> 4) * 8;

    float acc[4][4][4];
#pragma unroll
    for (int i = 0; i < 4; i++)
#pragma unroll
        for (int j = 0; j < 4; j++)
#pragma unroll
            for (int k = 0; k < 4; k++) acc[i][j][k] = 0.f;

#pragma unroll 1
    for (int s = 0; s < 9; s++) {
        if (s < 8) load_A_f16(sm, sum2, RREL * HDIM, s * HDIM, m0, M, tid);
        else       load_A_f16(sm, h1, HDIM, 0, m0, M, tid);
        load_B_f32(sm, (s < 8) ? (w2 + (size_t)s * HDIM * HDIM) : root2, tid);
        __syncthreads();
        compute_planes(sb, wm, wn, lrow, lhalf, acc);
        __syncthreads();
    }

    float* redA = (float*)sm;
    float* redB = (float*)sm + 512;
#pragma unroll
    for (int mf = 0; mf < 4; mf++) {
        float p0a = 0.f, p0b = 0.f, p1a = 0.f, p1b = 0.f;
#pragma unroll
        for (int nf = 0; nf < 4; nf++) {
            int cl = wn + nf * 8 + (lane & 3) * 2;
            float b0 = b2[cl], b1v = b2[cl + 1];
            float w00 = clsw[cl * 2], w01 = clsw[cl * 2 + 1];
            float w10 = clsw[(cl + 1) * 2], w11 = clsw[(cl + 1) * 2 + 1];
            float v0 = fmaxf(acc[mf][nf][0] + b0, 0.f);
            float v1 = fmaxf(acc[mf][nf][1] + b1v, 0.f);
            float v2 = fmaxf(acc[mf][nf][2] + b0, 0.f);
            float v3 = fmaxf(acc[mf][nf][3] + b1v, 0.f);
            p0a += v0 * w00 + v1 * w10; p0b += v0 * w01 + v1 * w11;
            p1a += v2 * w00 + v3 * w10; p1b += v2 * w01 + v3 * w11;
        }
#pragma unroll
        for (int o = 1; o <= 2; o <<= 1) {
            p0a += __shfl_xor_sync(0xffffffffu, p0a, o);
            p0b += __shfl_xor_sync(0xffffffffu, p0b, o);
            p1a += __shfl_xor_sync(0xffffffffu, p1a, o);
            p1b += __shfl_xor_sync(0xffffffffu, p1b, o);
        }
        if ((lane & 3) == 0) {
            int r0 = wm + mf * 16 + (lane >> 2);
            redA[r0 * 4 + (warp & 3)] = p0a;
            redB[r0 * 4 + (warp & 3)] = p0b;
            redA[(r0 + 8) * 4 + (warp & 3)] = p1a;
            redB[(r0 + 8) * 4 + (warp & 3)] = p1b;
        }
    }
    __syncthreads();
    if (tid < 128) {
        int gr = m0 + tid;
        if (gr < M) {
            float o0 = redA[tid * 4] + redA[tid * 4 + 1] + redA[tid * 4 + 2] + redA[tid * 4 + 3] + clsb[0];
            float o1 = redB[tid * 4] + redB[tid * 4 + 1] + redB[tid * 4 + 2] + redB[tid * 4 + 3] + clsb[1];
            out[gr * 2 + 0] = o0;
            out[gr * 2 + 1] = o1;
        }
    }
}

// ---------------- driver (single stream) -------------------------------------
extern "C" void kernel_launch(void* const* d_in, const int* in_sizes, int n_in,
                              void* d_out, int out_size) {
    const float* x     = (const float*)d_in[0];
    const int*   er    = (const int*)d_in[1];
    const int*   ea    = (const int*)d_in[2];
    const int*   et    = (const int*)d_in[3];
    const float* mlp_w = (const float*)d_in[4];
    const float* mlp_b = (const float*)d_in[5];
    const float* w1    = (const float*)d_in[6];
    const float* root1 = (const float*)d_in[7];
    const float* b1    = (const float*)d_in[8];
    const float* w2    = (const float*)d_in[9];
    const float* root2 = (const float*)d_in[10];
    const float* b2    = (const float*)d_in[11];
    const float* cls_w = (const float*)d_in[12];
    const float* cls_b = (const float*)d_in[13];
    int E = in_sizes[1];
    float* out = (float*)d_out;

    void *pH0, *pH1h, *pS2h;
    cudaGetSymbolAddress(&pH0, g_h0);
    cudaGetSymbolAddress(&pH1h, g_h1h);
    cudaGetSymbolAddress(&pS2h, g_sum2h);

    cudaFuncSetAttribute(y1root_k, cudaFuncAttributeMaxDynamicSharedMemorySize, MMA_SMEM);
    cudaFuncSetAttribute(l2_k, cudaFuncAttributeMaxDynamicSharedMemorySize, MMA_SMEM);

    const int GB = (NREPO + 127) / 128;   // 235

    // K1: zero counters | mlp | uroot (independent, block-range split)
    front_k<<<ZBLKS + MBLKS + UBLKS, 256>>>(x, mlp_w, mlp_b, root1);
    // K2-K6: CSR construction
    count_k<<<(E + 255) / 256, 256>>>(er, ea, et, E);
    scan_blk_all_k<<<NB1 + NB2, 1024>>>();
    scan_top_all_k<<<2, 1024>>>();
    scan_add_all_k<<<(B1 + B2 + 255) / 256, 256>>>();
    place_k<<<(E + 255) / 256, 256>>>(er, ea, et, E);
    // K7: y1 (8 relations) + root1, A tile loaded once per block
    y1root_k<<<dim3(GB, 1, 5), 256, MMA_SMEM>>>((const float*)pH0, NREPO, w1, root1, b1);
    // K8: layer-1 aggregation (actor rows of h1h)
    agg1_k<<<(NUSER * 32 + 255) / 256, 256>>>(b1, E);
    // K9: layer-2 aggregation -> fp16 means
    agg2_k<<<((size_t)B2 * 32 + 255) / 256, 256>>>();
    // K10: fused layer-2 dense + classifier
    l2_k<<<GB, 256, MMA_SMEM>>>(
        (const __half*)pS2h, (const __half*)pH1h, w2, root2, b2, cls_w, cls_b, out, NREPO);
}

// round 11
// speedup vs baseline: 2.2169x; 1.0388x over previous
#include <cuda_runtime.h>
#include <cuda_bf16.h>
#include <cuda_fp16.h>
#include <cstdint>

#define NREPO 30000
#define NUSER 70000
#define NNODE 100000
#define RREL  8
#define HDIM  128
#define B1 (NUSER * RREL)
#define B2 (NREPO * RREL)
#define NB1 ((B1 + 1023) / 1024)
#define NB2 ((B2 + 1023) / 1024)
#define EMAX 1000000

// fused front kernel block ranges
#define ZBLKS ((B1 + 255) / 256)
#define MBLKS ((NREPO * HDIM + 255) / 256)
#define UBLKS (HDIM / 2)

// ---------------- scratch ----------------------------------------------------
__device__ float  g_h0[(size_t)NREPO * HDIM];
__device__ __half g_h1h[(size_t)NNODE * HDIM];
__device__ __half g_y1h[(size_t)B2 * HDIM];
__device__ __half g_sum2h[(size_t)B2 * HDIM];
__device__ float  g_uroot[HDIM];
__device__ int    g_cnt1[B1], g_off1[B1], g_cur1[B1], g_bsum1[NB1];
__device__ int    g_cnt2[B2], g_off2[B2], g_cur2[B2], g_bsum2[NB2];
__device__ int    g_perm1[EMAX];
__device__ int    g_perm2[EMAX];

// ---------------- fused front: zero counters | mlp | uroot -------------------
__global__ void front_k(const float* __restrict__ x, const float* __restrict__ mlp_w,
                        const float* __restrict__ mlp_b, const float* __restrict__ root1) {
    int bx = blockIdx.x;
    int tid = threadIdx.x;
    if (bx < ZBLKS) {
        int i = bx * 256 + tid;
        if (i < B1) g_cnt1[i] = 0;
        if (i < B2) g_cnt2[i] = 0;
        return;
    }
    bx -= ZBLKS;
    if (bx < MBLKS) {
        int g = bx * 256 + tid;
        if (g >= NREPO * HDIM) return;
        int n = g >> 7, o = g & 127;
        float acc = mlp_b[o];
#pragma unroll
        for (int k = 0; k < 8; k++)
            acc = fmaf(__ldg(&x[n * 8 + k]), __ldg(&mlp_w[k * HDIM + o]), acc);
        g_h0[g] = fmaxf(acc, 0.f);
        return;
    }
    bx -= MBLKS;
    {
        int half = tid >> 7;
        int k = tid & 127;
        int o = bx * 2 + half;
        float v = fmaxf(mlp_b[k], 0.f) * root1[k * HDIM + o];
#pragma unroll
        for (int d = 16; d; d >>= 1) v += __shfl_xor_sync(0xffffffffu, v, d);
        __shared__ float s[8];
        int w = tid >> 5;
        if ((tid & 31) == 0) s[w] = v;
        __syncthreads();
        if (k == 0) g_uroot[o] = s[half * 4] + s[half * 4 + 1] + s[half * 4 + 2] + s[half * 4 + 3];
    }
}

// ---------------- counting / CSR build ---------------------------------------
__global__ void count_k(const int* __restrict__ er, const int* __restrict__ ea,
                        const int* __restrict__ et, int E) {
    int e = blockIdx.x * blockDim.x + threadIdx.x;
    if (e >= E) return;
    atomicAdd(&g_cnt1[ea[e] * RREL + et[e]], 1);
    atomicAdd(&g_cnt2[er[e] * RREL + et[e]], 1);
}

__global__ void scan_blk_all_k() {
    __shared__ int s[1024];
    int t = threadIdx.x;
    bool first = blockIdx.x < NB1;
    int blk = first ? blockIdx.x : blockIdx.x - NB1;
    const int* cnt = first ? g_cnt1 : g_cnt2;
    int* off = first ? g_off1 : g_off2;
    int* bsum = first ? g_bsum1 : g_bsum2;
    int n = first ? B1 : B2;
    int i = blk * 1024 + t;
    int v = (i < n) ? cnt[i] : 0;
    s[t] = v;
    __syncthreads();
#pragma unroll
    for (int d = 1; d < 1024; d <<= 1) {
        int u = (t >= d) ? s[t - d] : 0;
        __syncthreads();
        s[t] += u;
        __syncthreads();
    }
    if (i < n) off[i] = s[t] - v;
    if (t == 1023) bsum[blk] = s[1023];
}

__global__ void scan_top_all_k() {
    __shared__ int s[1024];
    int t = threadIdx.x;
    int* bsum = (blockIdx.x == 0) ? g_bsum1 : g_bsum2;
    int n = (blockIdx.x == 0) ? NB1 : NB2;
    int v = (t < n) ? bsum[t] : 0;
    s[t] = v;
    __syncthreads();
#pragma unroll
    for (int d = 1; d < 1024; d <<= 1) {
        int u = (t >= d) ? s[t - d] : 0;
        __syncthreads();
        s[t] += u;
        __syncthreads();
    }
    if (t < n) bsum[t] = s[t] - v;
}

__global__ void scan_add_all_k() {
    int i = blockIdx.x * blockDim.x + threadIdx.x;
    if (i < B1) {
        int o = g_off1[i] + g_bsum1[i >> 10];
        g_off1[i] = o;
        g_cur1[i] = o;
    } else if (i < B1 + B2) {
        int j = i - B1;
        int o = g_off2[j] + g_bsum2[j >> 10];
        g_off2[j] = o;
        g_cur2[j] = o;
    }
}

__global__ void place_k(const int* __restrict__ er, const int* __restrict__ ea,
                        const int* __restrict__ et, int E) {
    int e = blockIdx.x * blockDim.x + threadIdx.x;
    if (e >= E) return;
    int repo = er[e], actor = ea[e], t = et[e];
    int p1 = atomicAdd(&g_cur1[actor * RREL + t], 1);
    g_perm1[p1] = repo * RREL + t;
    int p2 = atomicAdd(&g_cur2[repo * RREL + t], 1);
    g_perm2[p2] = actor;
}

// ---------------- aggregations ------------------------------------------------
// layer-1: HALF-WARP per actor; lane16 covers 16B (8 halfs) of the 256B row.
__global__ void agg1_k(const float* __restrict__ b1, int E) {
    int hw = (blockIdx.x * blockDim.x + threadIdx.x) >> 4;   // actor
    int lane = threadIdx.x & 31;
    int lane16 = lane & 15;
    unsigned seg = 0xFFFFu << (lane & 16);                    // half-warp mask
    if (hw >= NUSER) return;
    float invreg = 0.f;
    if (lane16 < RREL) {
        int d = g_cnt1[hw * RREL + lane16];
        invreg = d ? 1.0f / (float)d : 0.f;
    }
    int start = g_off1[hw * RREL];
    int end = (hw * RREL + RREL < B1) ? g_off1[hw * RREL + RREL] : E;

    float a0, a1, a2, a3, a4, a5, a6, a7;
    {
        float4 ua = *(const float4*)(g_uroot + lane16 * 8);
        float4 ub = *(const float4*)(g_uroot + lane16 * 8 + 4);
        a0 = ua.x; a1 = ua.y; a2 = ua.z; a3 = ua.w;
        a4 = ub.x; a5 = ub.y; a6 = ub.z; a7 = ub.w;
    }

#define ACC1(u, iv) { \
        float2 f0 = __half22float2(((const __half2*)&(u))[0]); \
        float2 f1 = __half22float2(((const __half2*)&(u))[1]); \
        float2 f2 = __half22float2(((const __half2*)&(u))[2]); \
        float2 f3 = __half22float2(((const __half2*)&(u))[3]); \
        a0 = fmaf(f0.x, (iv), a0); a1 = fmaf(f0.y, (iv), a1); \
        a2 = fmaf(f1.x, (iv), a2); a3 = fmaf(f1.y, (iv), a3); \
        a4 = fmaf(f2.x, (iv), a4); a5 = fmaf(f2.y, (iv), a5); \
        a6 = fmaf(f3.x, (iv), a6); a7 = fmaf(f3.y, (iv), a7); }

    int j = start;
    for (; j + 4 <= end; j += 4) {
        int p0 = __ldg(g_perm1 + j),     p1 = __ldg(g_perm1 + j + 1);
        int p2 = __ldg(g_perm1 + j + 2), p3 = __ldg(g_perm1 + j + 3);
        uint4 u0 = *(const uint4*)(g_y1h + (((size_t)p0) << 7) + lane16 * 8);
        uint4 u1 = *(const uint4*)(g_y1h + (((size_t)p1) << 7) + lane16 * 8);
        uint4 u2 = *(const uint4*)(g_y1h + (((size_t)p2) << 7) + lane16 * 8);
        uint4 u3 = *(const uint4*)(g_y1h + (((size_t)p3) << 7) + lane16 * 8);
        float iv0 = __shfl_sync(seg, invreg, (p0 & 7) | (lane & 16));
        float iv1 = __shfl_sync(seg, invreg, (p1 & 7) | (lane & 16));
        float iv2 = __shfl_sync(seg, invreg, (p2 & 7) | (lane & 16));
        float iv3 = __shfl_sync(seg, invreg, (p3 & 7) | (lane & 16));
        ACC1(u0, iv0) ACC1(u1, iv1) ACC1(u2, iv2) ACC1(u3, iv3)
    }
    for (; j < end; j++) {
        int p0 = __ldg(g_perm1 + j);
        uint4 u0 = *(const uint4*)(g_y1h + (((size_t)p0) << 7) + lane16 * 8);
        float iv0 = __shfl_sync(seg, invreg, (p0 & 7) | (lane & 16));
        ACC1(u0, iv0)
    }
#undef ACC1

    float4 ba = *(const float4*)(b1 + lane16 * 8);
    float4 bb = *(const float4*)(b1 + lane16 * 8 + 4);
    uint4 pk;
    __half2 h0 = __floats2half2_rn(fmaxf(a0 + ba.x, 0.f), fmaxf(a1 + ba.y, 0.f));
    __half2 h1 = __floats2half2_rn(fmaxf(a2 + ba.z, 0.f), fmaxf(a3 + ba.w, 0.f));
    __half2 h2 = __floats2half2_rn(fmaxf(a4 + bb.x, 0.f), fmaxf(a5 + bb.y, 0.f));
    __half2 h3 = __floats2half2_rn(fmaxf(a6 + bb.z, 0.f), fmaxf(a7 + bb.w, 0.f));
    pk.x = *(unsigned*)&h0; pk.y = *(unsigned*)&h1;
    pk.z = *(unsigned*)&h2; pk.w = *(unsigned*)&h3;
    *(uint4*)(g_h1h + (((size_t)(NREPO + hw)) << 7) + lane16 * 8) = pk;
}

// layer-2: HALF-WARP per (repo, relation) bin, uint4 loads, 4-way unroll
__global__ void agg2_k() {
    int bin = (blockIdx.x * blockDim.x + threadIdx.x) >> 4;
    int lane16 = threadIdx.x & 15;
    if (bin >= B2) return;
    int deg = g_cnt2[bin];
    int start = g_off2[bin];
    float a0 = 0.f, a1 = 0.f, a2 = 0.f, a3 = 0.f, a4 = 0.f, a5 = 0.f, a6 = 0.f, a7 = 0.f;
#define ACC2(u) { \
        float2 f0 = __half22float2(((const __half2*)&(u))[0]); \
        float2 f1 = __half22float2(((const __half2*)&(u))[1]); \
        float2 f2 = __half22float2(((const __half2*)&(u))[2]); \
        float2 f3 = __half22float2(((const __half2*)&(u))[3]); \
        a0 += f0.x; a1 += f0.y; a2 += f1.x; a3 += f1.y; \
        a4 += f2.x; a5 += f2.y; a6 += f3.x; a7 += f3.y; }
    int j = 0;
    for (; j + 4 <= deg; j += 4) {
        int c0 = __ldg(g_perm2 + start + j);
        int c1 = __ldg(g_perm2 + start + j + 1);
        int c2 = __ldg(g_perm2 + start + j + 2);
        int c3 = __ldg(g_perm2 + start + j + 3);
        uint4 u0 = *(const uint4*)(g_h1h + (((size_t)(NREPO + c0)) << 7) + lane16 * 8);
        uint4 u1 = *(const uint4*)(g_h1h + (((size_t)(NREPO + c1)) << 7) + lane16 * 8);
        uint4 u2 = *(const uint4*)(g_h1h + (((size_t)(NREPO + c2)) << 7) + lane16 * 8);
        uint4 u3 = *(const uint4*)(g_h1h + (((size_t)(NREPO + c3)) << 7) + lane16 * 8);
        ACC2(u0) ACC2(u1) ACC2(u2) ACC2(u3)
    }
    for (; j < deg; j++) {
        int c0 = __ldg(g_perm2 + start + j);
        uint4 u0 = *(const uint4*)(g_h1h + (((size_t)(NREPO + c0)) << 7) + lane16 * 8);
        ACC2(u0)
    }
#undef ACC2
    float inv = deg ? 1.0f / (float)deg : 0.f;
    uint4 pk;
    __half2 h0 = __floats2half2_rn(a0 * inv, a1 * inv);
    __half2 h1 = __floats2half2_rn(a2 * inv, a3 * inv);
    __half2 h2 = __floats2half2_rn(a4 * inv, a5 * inv);
    __half2 h3 = __floats2half2_rn(a6 * inv, a7 * inv);
    pk.x = *(unsigned*)&h0; pk.y = *(unsigned*)&h1;
    pk.z = *(unsigned*)&h2; pk.w = *(unsigned*)&h3;
    *(uint4*)(g_sum2h + ((size_t)bin << 7) + lane16 * 8) = pk;
}

// ================= bf16 3-term tensor-core GEMM pieces =======================
#define PITCH 136
#define AH_OFF 0
#define AL_OFF 34816
#define BH_OFF 69632
#define BL_OFF 104448
#define MMA_SMEM 139264

__device__ __forceinline__ uint32_t smem_u32(const void* p) {
    uint32_t a;
    asm("{ .reg .u64 t; cvta.to.shared.u64 t, %1; cvt.u32.u64 %0, t; }" : "=r"(a) : "l"(p));
    return a;
}

__device__ __forceinline__ void ldsm_x4(unsigned r[4], uint32_t addr) {
    asm volatile("ldmatrix.sync.aligned.m8n8.x4.shared.b16 {%0,%1,%2,%3}, [%4];"
                 : "=r"(r[0]), "=r"(r[1]), "=r"(r[2]), "=r"(r[3]) : "r"(addr));
}

__device__ __forceinline__ void ldsm_x4_t(unsigned r[4], uint32_t addr) {
    asm volatile("ldmatrix.sync.aligned.m8n8.x4.trans.shared.b16 {%0,%1,%2,%3}, [%4];"
                 : "=r"(r[0]), "=r"(r[1]), "=r"(r[2]), "=r"(r[3]) : "r"(addr));
}

__device__ __forceinline__ void mma_bf16(float c[4], const unsigned a[4], const unsigned* b) {
    asm volatile(
        "mma.sync.aligned.m16n8k16.row.col.f32.bf16.bf16.f32 "
        "{%0,%1,%2,%3}, {%4,%5,%6,%7}, {%8,%9}, {%0,%1,%2,%3};"
        : "+f"(c[0]), "+f"(c[1]), "+f"(c[2]), "+f"(c[3])
        : "r"(a[0]), "r"(a[1]), "r"(a[2]), "r"(a[3]), "r"(b[0]), "r"(b[1]));
}

__device__ __forceinline__ void sp_bf(float x, unsigned short& h, unsigned short& l) {
    __nv_bfloat16 hb = __float2bfloat16_rn(x);
    h = __bfloat16_as_ushort(hb);
    l = __bfloat16_as_ushort(__float2bfloat16_rn(x - __bfloat162float(hb)));
}

__device__ __forceinline__ void store_planes(char* sm, int plane_off_h, int plane_off_l,
                                             int row, int c4, float4 f) {
    unsigned short h0, h1, h2, h3, l0, l1, l2, l3;
    sp_bf(f.x, h0, l0); sp_bf(f.y, h1, l1); sp_bf(f.z, h2, l2); sp_bf(f.w, h3, l3);
    int off = (row * PITCH + c4) * 2;
    *(uint2*)(sm + plane_off_h + off) = make_uint2((unsigned)h0 | ((unsigned)h1 << 16),
                                                   (unsigned)h2 | ((unsigned)h3 << 16));
    *(uint2*)(sm + plane_off_l + off) = make_uint2((unsigned)l0 | ((unsigned)l1 << 16),
                                                   (unsigned)l2 | ((unsigned)l3 << 16));
}

__device__ __forceinline__ void load_A_f32(char* sm, const float* __restrict__ A, int lda,
                                           int m0, int M, int tid) {
#pragma unroll
    for (int it = 0; it < 16; it++) {
        int v = tid + it * 256;
        int row = v >> 5;
        int c4 = (v & 31) * 4;
        float4 fa = (m0 + row < M) ? *(const float4*)(A + (size_t)(m0 + row) * lda + c4)
                                   : make_float4(0.f, 0.f, 0.f, 0.f);
        store_planes(sm, AH_OFF, AL_OFF, row, c4, fa);
    }
}

__device__ __forceinline__ void load_A_f16(char* sm, const __half* __restrict__ A, int lda,
                                           int cO, int m0, int M, int tid) {
#pragma unroll
    for (int it = 0; it < 16; it++) {
        int v = tid + it * 256;
        int row = v >> 5;
        int c4 = (v & 31) * 4;
        float4 fa = make_float4(0.f, 0.f, 0.f, 0.f);
        if (m0 + row < M) {
            uint2 u = *(const uint2*)(A + (size_t)(m0 + row) * lda + cO + c4);
            float2 lo = __half22float2(((const __half2*)&u)[0]);
            float2 hi = __half22float2(((const __half2*)&u)[1]);
            fa = make_float4(lo.x, lo.y, hi.x, hi.y);
        }
        store_planes(sm, AH_OFF, AL_OFF, row, c4, fa);
    }
}

__device__ __forceinline__ void load_B_f32(char* sm, const float* __restrict__ B, int tid) {
#pragma unroll
    for (int it = 0; it < 16; it++) {
        int v = tid + it * 256;
        int row = v >> 5;
        int c4 = (v & 31) * 4;
        float4 fb = *(const float4*)(B + (size_t)row * 128 + c4);
        store_planes(sm, BH_OFF, BL_OFF, row, c4, fb);
    }
}

__device__ __forceinline__ void compute_planes(uint32_t sb, int wm, int wn, int lrow,
                                               int lhalf, float (&acc)[4][4][4]) {
#pragma unroll 1
    for (int kc = 0; kc < 8; kc++) {
        int k0 = kc * 16;
        unsigned Ah[4][4], Al[4][4], Bh[2][4], Bl[2][4];
#pragma unroll
        for (int mf = 0; mf < 4; mf++) {
            uint32_t a = sb + ((wm + mf * 16 + lrow) * PITCH + k0 + lhalf) * 2;
            ldsm_x4(Ah[mf], a + AH_OFF);
            ldsm_x4(Al[mf], a + AL_OFF);
        }
#pragma unroll
        for (int np = 0; np < 2; np++) {
            uint32_t a = sb + ((k0 + lrow) * PITCH + wn + np * 16 + lhalf) * 2;
            ldsm_x4_t(Bh[np], a + BH_OFF);
            ldsm_x4_t(Bl[np], a + BL_OFF);
        }
#pragma unroll
        for (int mf = 0; mf < 4; mf++)
#pragma unroll
            for (int nf = 0; nf < 4; nf++) {
                const unsigned* bh = &Bh[nf >> 1][(nf & 1) * 2];
                const unsigned* bl = &Bl[nf >> 1][(nf & 1) * 2];
                mma_bf16(acc[mf][nf], Ah[mf], bh);
                mma_bf16(acc[mf][nf], Al[mf], bh);
                mma_bf16(acc[mf][nf], Ah[mf], bl);
            }
    }
}

// y1 + root1 fused
__global__ void __launch_bounds__(256)
y1root_k(const float* __restrict__ A, int M, const float* __restrict__ w1,
         const float* __restrict__ root1, const float* __restrict__ bias) {
    extern __shared__ char sm[];
    const uint32_t sb = smem_u32(sm);
    const int tid = threadIdx.x;
    const int lane = tid & 31;
    const int warp = tid >> 5;
    const int wm = (warp >> 2) * 64;
    const int wn = (warp & 3) * 32;
    const int m0 = blockIdx.x * 128;
    const int lrow = lane & 15;
    const int lhalf = (lane >> 4) * 8;
    const int z = blockIdx.z;
    const int nmat = (z == 4) ? 1 : 2;

    load_A_f32(sm, A, HDIM, m0, M, tid);

#pragma unroll 1
    for (int rr = 0; rr < nmat; rr++) {
        const float* B = (z == 4) ? root1 : (w1 + (size_t)(z * 2 + rr) * HDIM * HDIM);
        load_B_f32(sm, B, tid);
        __syncthreads();

        float acc[4][4][4];
#pragma unroll
        for (int i = 0; i < 4; i++)
#pragma unroll
            for (int j = 0; j < 4; j++)
#pragma unroll
                for (int k = 0; k < 4; k++) acc[i][j][k] = 0.f;

        compute_planes(sb, wm, wn, lrow, lhalf, acc);

#pragma unroll
        for (int mf = 0; mf < 4; mf++)
#pragma unroll
            for (int nf = 0; nf < 4; nf++) {
                int r0 = m0 + wm + mf * 16 + (lane >> 2);
                int r1 = r0 + 8;
                int cl = wn + nf * 8 + (lane & 3) * 2;
                if (z == 4) {
                    float b0 = bias[cl], b1v = bias[cl + 1];
                    if (r0 < M)
                        *(__half2*)(g_h1h + (size_t)r0 * HDIM + cl) =
                            __floats2half2_rn(fmaxf(acc[mf][nf][0] + b0, 0.f),
                                              fmaxf(acc[mf][nf][1] + b1v, 0.f));
                    if (r1 < M)
                        *(__half2*)(g_h1h + (size_t)r1 * HDIM + cl) =
                            __floats2half2_rn(fmaxf(acc[mf][nf][2] + b0, 0.f),
                                              fmaxf(acc[mf][nf][3] + b1v, 0.f));
                } else {
                    int r = z * 2 + rr;
                    if (r0 < M)
                        *(__half2*)(g_y1h + (size_t)r0 * (RREL * HDIM) + r * HDIM + cl) =
                            __floats2half2_rn(acc[mf][nf][0], acc[mf][nf][1]);
                    if (r1 < M)
                        *(__half2*)(g_y1h + (size_t)r1 * (RREL * HDIM) + r * HDIM + cl) =
                            __floats2half2_rn(acc[mf][nf][2], acc[mf][nf][3]);
                }
            }
        __syncthreads();
    }
}

// fused layer-2 + classifier
__global__ void __launch_bounds__(256)
l2_k(const __half* __restrict__ sum2, const __half* __restrict__ h1,
     const float* __restrict__ w2, const float* __restrict__ root2,
     const float* __restrict__ b2, const float* __restrict__ clsw,
     const float* __restrict__ clsb, float* __restrict__ out, int M) {
    extern __shared__ char sm[];
    const uint32_t sb = smem_u32(sm);
    const int tid = threadIdx.x;
    const int lane = tid & 31;
    const int warp = tid >> 5;
    const int wm = (warp >> 2) * 64;
    const int wn = (warp & 3) * 32;
    const int m0 = blockIdx.x * 128;
    const int lrow = lane & 15;
    const int lhalf = (lane >> 4) * 8;

    float acc[4][4][4];
#pragma unroll
    for (int i = 0; i < 4; i++)
#pragma unroll
        for (int j = 0; j < 4; j++)
#pragma unroll
            for (int k = 0; k < 4; k++) acc[i][j][k] = 0.f;

#pragma unroll 1
    for (int s = 0; s < 9; s++) {
        if (s < 8) load_A_f16(sm, sum2, RREL * HDIM, s * HDIM, m0, M, tid);
        else       load_A_f16(sm, h1, HDIM, 0, m0, M, tid);
        load_B_f32(sm, (s < 8) ? (w2 + (size_t)s * HDIM * HDIM) : root2, tid);
        __syncthreads();
        compute_planes(sb, wm, wn, lrow, lhalf, acc);
        __syncthreads();
    }

    float* redA = (float*)sm;
    float* redB = (float*)sm + 512;
#pragma unroll
    for (int mf = 0; mf < 4; mf++) {
        float p0a = 0.f, p0b = 0.f, p1a = 0.f, p1b = 0.f;
#pragma unroll
        for (int nf = 0; nf < 4; nf++) {
            int cl = wn + nf * 8 + (lane & 3) * 2;
            float b0 = b2[cl], b1v = b2[cl + 1];
            float w00 = clsw[cl * 2], w01 = clsw[cl * 2 + 1];
            float w10 = clsw[(cl + 1) * 2], w11 = clsw[(cl + 1) * 2 + 1];
            float v0 = fmaxf(acc[mf][nf][0] + b0, 0.f);
            float v1 = fmaxf(acc[mf][nf][1] + b1v, 0.f);
            float v2 = fmaxf(acc[mf][nf][2] + b0, 0.f);
            float v3 = fmaxf(acc[mf][nf][3] + b1v, 0.f);
            p0a += v0 * w00 + v1 * w10; p0b += v0 * w01 + v1 * w11;
            p1a += v2 * w00 + v3 * w10; p1b += v2 * w01 + v3 * w11;
        }
#pragma unroll
        for (int o = 1; o <= 2; o <<= 1) {
            p0a += __shfl_xor_sync(0xffffffffu, p0a, o);
            p0b += __shfl_xor_sync(0xffffffffu, p0b, o);
            p1a += __shfl_xor_sync(0xffffffffu, p1a, o);
            p1b += __shfl_xor_sync(0xffffffffu, p1b, o);
        }
        if ((lane & 3) == 0) {
            int r0 = wm + mf * 16 + (lane >> 2);
            redA[r0 * 4 + (warp & 3)] = p0a;
            redB[r0 * 4 + (warp & 3)] = p0b;
            redA[(r0 + 8) * 4 + (warp & 3)] = p1a;
            redB[(r0 + 8) * 4 + (warp & 3)] = p1b;
        }
    }
    __syncthreads();
    if (tid < 128) {
        int gr = m0 + tid;
        if (gr < M) {
            float o0 = redA[tid * 4] + redA[tid * 4 + 1] + redA[tid * 4 + 2] + redA[tid * 4 + 3] + clsb[0];
            float o1 = redB[tid * 4] + redB[tid * 4 + 1] + redB[tid * 4 + 2] + redB[tid * 4 + 3] + clsb[1];
            out[gr * 2 + 0] = o0;
            out[gr * 2 + 1] = o1;
        }
    }
}

// ---------------- driver (single stream) -------------------------------------
extern "C" void kernel_launch(void* const* d_in, const int* in_sizes, int n_in,
                              void* d_out, int out_size) {
    const float* x     = (const float*)d_in[0];
    const int*   er    = (const int*)d_in[1];
    const int*   ea    = (const int*)d_in[2];
    const int*   et    = (const int*)d_in[3];
    const float* mlp_w = (const float*)d_in[4];
    const float* mlp_b = (const float*)d_in[5];
    const float* w1    = (const float*)d_in[6];
    const float* root1 = (const float*)d_in[7];
    const float* b1    = (const float*)d_in[8];
    const float* w2    = (const float*)d_in[9];
    const float* root2 = (const float*)d_in[10];
    const float* b2    = (const float*)d_in[11];
    const float* cls_w = (const float*)d_in[12];
    const float* cls_b = (const float*)d_in[13];
    int E = in_sizes[1];
    float* out = (float*)d_out;

    void *pH0, *pH1h, *pS2h;
    cudaGetSymbolAddress(&pH0, g_h0);
    cudaGetSymbolAddress(&pH1h, g_h1h);
    cudaGetSymbolAddress(&pS2h, g_sum2h);

    cudaFuncSetAttribute(y1root_k, cudaFuncAttributeMaxDynamicSharedMemorySize, MMA_SMEM);
    cudaFuncSetAttribute(l2_k, cudaFuncAttributeMaxDynamicSharedMemorySize, MMA_SMEM);

    const int GB = (NREPO + 127) / 128;   // 235

    // K1: zero counters | mlp | uroot
    front_k<<<ZBLKS + MBLKS + UBLKS, 256>>>(x, mlp_w, mlp_b, root1);
    // K2-K6: CSR construction
    count_k<<<(E + 255) / 256, 256>>>(er, ea, et, E);
    scan_blk_all_k<<<NB1 + NB2, 1024>>>();
    scan_top_all_k<<<2, 1024>>>();
    scan_add_all_k<<<(B1 + B2 + 255) / 256, 256>>>();
    place_k<<<(E + 255) / 256, 256>>>(er, ea, et, E);
    // K7: y1 (8 relations) + root1
    y1root_k<<<dim3(GB, 1, 5), 256, MMA_SMEM>>>((const float*)pH0, NREPO, w1, root1, b1);
    // K8: layer-1 aggregation (half-warp per actor, uint4 loads)
    agg1_k<<<(NUSER * 16 + 255) / 256, 256>>>(b1, E);
    // K9: layer-2 aggregation (half-warp per bin, uint4 loads)
    agg2_k<<<((size_t)B2 * 16 + 255) / 256, 256>>>();
    // K10: fused layer-2 dense + classifier
    l2_k<<<GB, 256, MMA_SMEM>>>(
        (const __half*)pS2h, (const __half*)pH1h, w2, root2, b2, cls_w, cls_b, out, NREPO);
}